// round 12
// baseline (speedup 1.0000x reference)
#include <cuda_runtime.h>
#include <cuda_bf16.h>
#include <cstdint>
#include <cmath>

#define B_  64
#define T_  512
#define E_  512
#define H_  1024
#define M_  (B_*T_)     // 32768 rows
#define G3_ (3*H_)      // 3072

extern __shared__ char hx_smem[];

// ---------------- scratch ----------------
__device__ float g_xg [(size_t)M_ * G3_];
__device__ float g_buf0[(size_t)M_ * H_];
__device__ float g_h[2][B_ * H_];
__device__ __nv_bfloat16 g_hhi[2][B_ * H_];
__device__ __nv_bfloat16 g_hlo[2][B_ * H_];
__device__ __nv_bfloat16 g_ahi[(size_t)M_ * H_];
__device__ __nv_bfloat16 g_alo[(size_t)M_ * H_];
__device__ __nv_bfloat16 g_wthi[(size_t)G3_ * H_];       // Wx^T [N][K]
__device__ __nv_bfloat16 g_wtlo[(size_t)G3_ * H_];
__device__ __nv_bfloat16 g_whthi[(size_t)G3_ * H_];      // Wh^T [N][K] (standard rows)
__device__ __nv_bfloat16 g_whtlo[(size_t)G3_ * H_];
__device__ unsigned g_grp_cnt[8];
__device__ unsigned g_root_cnt = 0;
__device__ unsigned g_bar_gen  = 0;
__device__ int g_x_is_i64 = 1;

// ---------------- helpers ----------------
__device__ __forceinline__ float fast_tanh(float x) {
    float y; asm("tanh.approx.f32 %0, %1;" : "=f"(y) : "f"(x)); return y;
}
__device__ __forceinline__ float fast_sigmoid(float x) {
    return 0.5f * fast_tanh(0.5f * x) + 0.5f;
}
__device__ __forceinline__ uint32_t smem_u32(const void* p) {
    return (uint32_t)__cvta_generic_to_shared(p);
}
__device__ __forceinline__ void cp_async16(uint32_t smem_addr, const void* gptr) {
    asm volatile("cp.async.cg.shared.global [%0], [%1], 16;"
                 :: "r"(smem_addr), "l"(gptr));
}
__device__ __forceinline__ void cp_commit() { asm volatile("cp.async.commit_group;"); }
__device__ __forceinline__ void cp_wait0() { asm volatile("cp.async.wait_group 0;"); }
__device__ __forceinline__ void cp_wait1() { asm volatile("cp.async.wait_group 1;"); }

#define LDSM_X4(r, addr) \
    asm volatile("ldmatrix.sync.aligned.m8n8.x4.shared.b16 {%0,%1,%2,%3}, [%4];" \
        : "=r"((r)[0]), "=r"((r)[1]), "=r"((r)[2]), "=r"((r)[3]) : "r"(addr))

#define MMA16816(d, a, b0, b1) \
    asm volatile("mma.sync.aligned.m16n8k16.row.col.f32.bf16.bf16.f32 " \
        "{%0,%1,%2,%3}, {%4,%5,%6,%7}, {%8,%9}, {%0,%1,%2,%3};" \
        : "+f"((d)[0]), "+f"((d)[1]), "+f"((d)[2]), "+f"((d)[3]) \
        : "r"((a)[0]), "r"((a)[1]), "r"((a)[2]), "r"((a)[3]), "r"(b0), "r"(b1))

// ---------------- int64-vs-int32 detection ----------------
__global__ void detect_kernel(const int* __restrict__ x32) {
    __shared__ int nz;
    if (threadIdx.x == 0) nz = 0;
    __syncthreads();
    if (x32[2 * threadIdx.x + 1] != 0) atomicExch(&nz, 1);
    __syncthreads();
    if (threadIdx.x == 0) g_x_is_i64 = (nz == 0) ? 1 : 0;
}

// ---------------- embedding gather (direct bf16 hi/lo) + pad mask ----------------
__global__ __launch_bounds__(128) void embed_kernel(
    const void* __restrict__ xraw, const float* __restrict__ emb,
    __nv_bfloat16* __restrict__ ahi, __nv_bfloat16* __restrict__ alo,
    float* __restrict__ mask_out)
{
    const int r = blockIdx.x;
    long long idx;
    if (g_x_is_i64) idx = ((const long long*)xraw)[r];
    else            idx = (long long)((const int*)xraw)[r];
    float4 v = ((const float4*)(emb + (size_t)idx * E_))[threadIdx.x];
    union { __nv_bfloat16 b[4]; uint2 u; } Hh, Ll;
    float f[4] = {v.x, v.y, v.z, v.w};
#pragma unroll
    for (int q = 0; q < 4; q++) {
        __nv_bfloat16 h = __float2bfloat16_rn(f[q]);
        Hh.b[q] = h;
        Ll.b[q] = __float2bfloat16_rn(f[q] - __bfloat162float(h));
    }
    ((uint2*)(ahi + (size_t)r * E_))[threadIdx.x] = Hh.u;
    ((uint2*)(alo + (size_t)r * E_))[threadIdx.x] = Ll.u;
    if (threadIdx.x == 0) mask_out[r] = (idx != 0) ? 1.0f : 0.0f;
}

// ---------------- W [K][3072] fp32 -> W^T [3072][K] bf16 hi/lo ----------------
__global__ __launch_bounds__(256) void convertWT_kernel(
    const float* __restrict__ W, __nv_bfloat16* __restrict__ Thi,
    __nv_bfloat16* __restrict__ Tlo, int K)
{
    __shared__ float t[32][33];
    const int n0 = blockIdx.x * 32, k0 = blockIdx.y * 32;
    const int tx = threadIdx.x & 31, ty = threadIdx.x >> 5;
#pragma unroll
    for (int i = 0; i < 32; i += 8)
        t[ty + i][tx] = W[(size_t)(k0 + ty + i) * G3_ + n0 + tx];
    __syncthreads();
#pragma unroll
    for (int i = 0; i < 32; i += 8) {
        float v = t[tx][ty + i];
        __nv_bfloat16 h = __float2bfloat16_rn(v);
        size_t o = (size_t)(n0 + ty + i) * K + k0 + tx;
        Thi[o] = h;
        Tlo[o] = __float2bfloat16_rn(v - __bfloat162float(h));
    }
}

// ---------------- bf16-split mma.sync GEMM (unchanged, proven) -------
#define GT_TILE   18432                // 128 * 144
#define GT_STAGE  (4 * GT_TILE)
#define GT_SMEM   (2 * GT_STAGE)       // 147456 B

__global__ __launch_bounds__(256, 1) void gemm_mma_kernel(
    const __nv_bfloat16* __restrict__ Ahi, const __nv_bfloat16* __restrict__ Alo,
    const __nv_bfloat16* __restrict__ Bhi, const __nv_bfloat16* __restrict__ Blo,
    const float* __restrict__ bias, float* __restrict__ C, int K)
{
    const uint32_t sb = smem_u32(hx_smem);
    const int tid = threadIdx.x;
    const int wid = tid >> 5, lid = tid & 31;
    const int wm = wid & 1, wn = wid >> 1;
    const int n0 = blockIdx.x * 128, m0 = blockIdx.y * 128;
    const int nch = K >> 6;

    float acc[4][4][4];
#pragma unroll
    for (int mf = 0; mf < 4; mf++)
#pragma unroll
        for (int n8 = 0; n8 < 4; n8++)
#pragma unroll
            for (int q = 0; q < 4; q++) acc[mf][n8][q] = 0.0f;

    auto stage = [&](int kc) {
        const uint32_t st = sb + (uint32_t)(kc & 1) * GT_STAGE;
        const int koff = kc * 64;
#pragma unroll
        for (int q = 0; q < 4; q++) {
            int i = tid + 256 * q;
            int row = i >> 3, seg = i & 7;
            uint32_t d = st + (uint32_t)(row * 144 + seg * 16);
            size_t ao = (size_t)(m0 + row) * K + koff + seg * 8;
            size_t bo = (size_t)(n0 + row) * K + koff + seg * 8;
            cp_async16(d,               Ahi + ao);
            cp_async16(d + GT_TILE,     Alo + ao);
            cp_async16(d + 2 * GT_TILE, Bhi + bo);
            cp_async16(d + 3 * GT_TILE, Blo + bo);
        }
        cp_commit();
    };

    const int a_row = wm * 64 + (lid & 15);
    const int a_colb = (lid >> 4) * 16;
    const int b_row = wn * 32 + ((lid >> 4) << 3) + (lid & 7);
    const int b_colb = ((lid >> 3) & 1) * 16;

    stage(0);
    for (int c = 0; c < nch; c++) {
        if (c + 1 < nch) { stage(c + 1); cp_wait1(); }
        else             { cp_wait0(); }
        __syncthreads();

        const uint32_t st = sb + (uint32_t)(c & 1) * GT_STAGE;
#pragma unroll
        for (int ks = 0; ks < 4; ks++) {
            const int kb = ks * 32;
            uint32_t ah[4][4], al[4][4], bh[2][4], bl[2][4];
#pragma unroll
            for (int mf = 0; mf < 4; mf++) {
                uint32_t addr = st + (uint32_t)((a_row + mf * 16) * 144 + kb + a_colb);
                LDSM_X4(ah[mf], addr);
                LDSM_X4(al[mf], addr + GT_TILE);
            }
#pragma unroll
            for (int nf = 0; nf < 2; nf++) {
                uint32_t addr = st + 2 * GT_TILE +
                                (uint32_t)((b_row + nf * 16) * 144 + kb + b_colb);
                LDSM_X4(bh[nf], addr);
                LDSM_X4(bl[nf], addr + GT_TILE);
            }
#pragma unroll
            for (int mf = 0; mf < 4; mf++)
#pragma unroll
                for (int n8 = 0; n8 < 4; n8++) {
                    const int nf = n8 >> 1, hh = (n8 & 1) * 2;
                    MMA16816(acc[mf][n8], ah[mf], bh[nf][hh], bh[nf][hh + 1]);
                    MMA16816(acc[mf][n8], ah[mf], bl[nf][hh], bl[nf][hh + 1]);
                    MMA16816(acc[mf][n8], al[mf], bh[nf][hh], bh[nf][hh + 1]);
                }
        }
        __syncthreads();
    }

#pragma unroll
    for (int mf = 0; mf < 4; mf++) {
        const int gm = m0 + wm * 64 + mf * 16 + (lid >> 2);
#pragma unroll
        for (int n8 = 0; n8 < 4; n8++) {
            const int gc = n0 + wn * 32 + n8 * 8 + (lid & 3) * 2;
            float2 bb = *(const float2*)(bias + gc);
            float2 v0, v1;
            v0.x = acc[mf][n8][0] + bb.x; v0.y = acc[mf][n8][1] + bb.y;
            v1.x = acc[mf][n8][2] + bb.x; v1.y = acc[mf][n8][3] + bb.y;
            *(float2*)(C + (size_t)gm * G3_ + gc)       = v0;
            *(float2*)(C + (size_t)(gm + 8) * G3_ + gc) = v1;
        }
    }
}

// ---------------- gate-grouped tensor-core scan: ONE barrier per step --------
// 64 CTAs x 384 threads. Permuted gate columns p = 3*j + g: CTA c owns
// p in [48c, 48c+48) = ALL gates of units [16c, 16c+16). Update is CTA-local.
// W streamed from L2 per 128-k chunk (double-buffered with h staging).
#define SN_CTAS   64
#define SN_THREADS 384
#define SN_SR     272
#define SN_WCH    (48 * SN_SR)          // 13056
#define SN_ACH    (64 * SN_SR)          // 17408
#define SN_WB     0
#define SN_AB     (4 * SN_WCH)          // 52224
#define SN_XG     (SN_AB + 4 * SN_ACH)  // 121856
#define SN_GP     (SN_XG + 64*3*16*4)   // 134144
#define SN_BH     (SN_GP + 64*52*4)     // 147456
#define SN_SMEM   (SN_BH + 192)         // 147648

__device__ __forceinline__ void grid_barrier64(int c) {
    __syncthreads();
    if (threadIdx.x == 0) {
        __threadfence();
        unsigned gen = *(volatile unsigned*)&g_bar_gen;
        int grp = c & 7;                         // 8 groups x 8 CTAs
        if (atomicAdd(&g_grp_cnt[grp], 1u) == 7u) {
            if (atomicAdd(&g_root_cnt, 1u) == 7u) {
                atomicExch(&g_root_cnt, 0u);
#pragma unroll
                for (int i = 0; i < 8; i++) atomicExch(&g_grp_cnt[i], 0u);
                __threadfence();
                atomicAdd(&g_bar_gen, 1u);
            }
        }
        while (*(volatile unsigned*)&g_bar_gen == gen) { }
        __threadfence();
    }
    __syncthreads();
}

__global__ __launch_bounds__(SN_THREADS, 1) void scan_mma_kernel(
    const float* __restrict__ xg,
    const __nv_bfloat16* __restrict__ wthi, const __nv_bfloat16* __restrict__ wtlo,
    const float* __restrict__ bh, float* __restrict__ hout,
    __nv_bfloat16* __restrict__ ahi, __nv_bfloat16* __restrict__ alo,
    float* __restrict__ state_out)
{
    const uint32_t sb = smem_u32(hx_smem);
    const int c = blockIdx.x, tid = threadIdx.x;
    const int wid = tid >> 5, lid = tid & 31;
    const int wm = wid & 3, wn = wid >> 2;            // 4m x 3n warps
    float* sXg = (float*)(hx_smem + SN_XG);
    float* sGp = (float*)(hx_smem + SN_GP);
    float* sBh = (float*)(hx_smem + SN_BH);

    // permuted bias: row q -> gate q%3, unit 16c + q/3
    if (tid < 48) sBh[tid] = bh[(tid % 3) * H_ + 16 * c + tid / 3];
    for (int e = c * SN_THREADS + tid; e < B_ * H_; e += SN_CTAS * SN_THREADS) {
        g_h[0][e] = 0.0f;
        g_hhi[0][e] = __float2bfloat16(0.0f);
        g_hlo[0][e] = __float2bfloat16(0.0f);
    }
    grid_barrier64(c);

    const int a_row  = wm * 16 + (lid & 15);
    const int a_colb = (lid >> 4) * 16;
    const int b_row  = wn * 16 + ((lid >> 4) << 3) + (lid & 7);
    const int b_colb = ((lid >> 3) & 1) * 16;

    for (int t = 0; t < T_; t++) {
        const int par = t & 1, nxt = par ^ 1;
        const __nv_bfloat16* hhi = g_hhi[par];
        const __nv_bfloat16* hlo = g_hlo[par];

        // prefetch h_old into registers
        float ph[3];
#pragma unroll
        for (int it = 0; it < 3; it++) {
            int item = tid + it * SN_THREADS;
            if (item < 1024)
                ph[it] = g_h[par][((item >> 4) * H_) + 16 * c + (item & 15)];
        }

        auto stage = [&](int ck) {
            const uint32_t wb = sb + SN_WB + (uint32_t)((ck & 1) * 2 * SN_WCH);
            const uint32_t ab = sb + SN_AB + (uint32_t)((ck & 1) * 2 * SN_ACH);
            // W: 48 rows x 16 segs (permuted source rows)
            for (int i = tid; i < 768; i += SN_THREADS) {
                int row = i >> 4, seg = i & 15;
                int srow = (row % 3) * H_ + 16 * c + row / 3;
                size_t so = (size_t)srow * H_ + ck * 128 + seg * 8;
                uint32_t d = wb + (uint32_t)(row * SN_SR + seg * 16);
                cp_async16(d,          wthi + so);
                cp_async16(d + SN_WCH, wtlo + so);
            }
            // A (h): 64 rows x 16 segs
            for (int i = tid; i < 1024; i += SN_THREADS) {
                int row = i >> 4, seg = i & 15;
                size_t so = (size_t)row * H_ + ck * 128 + seg * 8;
                uint32_t d = ab + (uint32_t)(row * SN_SR + seg * 16);
                cp_async16(d,          hhi + so);
                cp_async16(d + SN_ACH, hlo + so);
            }
        };

        // stage chunk 0 + xg (one group)
        stage(0);
        for (int i = tid; i < 768; i += SN_THREADS) {
            int b = i / 12, r = i - 12 * b;
            int g = r >> 2, s = r & 3;
            const float* src = xg + ((size_t)b * T_ + t) * G3_ + g * H_ + 16 * c + s * 4;
            cp_async16(sb + SN_XG + (uint32_t)(((b * 3 + g) * 16 + s * 4) * 4), src);
        }
        cp_commit();

        float acc[2][4];
#pragma unroll
        for (int n8 = 0; n8 < 2; n8++)
#pragma unroll
            for (int q = 0; q < 4; q++) acc[n8][q] = 0.0f;

        for (int ck = 0; ck < 8; ck++) {
            if (ck + 1 < 8) { stage(ck + 1); cp_commit(); cp_wait1(); }
            else            { cp_wait0(); }
            __syncthreads();
            const uint32_t wb = sb + SN_WB + (uint32_t)((ck & 1) * 2 * SN_WCH);
            const uint32_t ab = sb + SN_AB + (uint32_t)((ck & 1) * 2 * SN_ACH);
#pragma unroll
            for (int ks = 0; ks < 8; ks++) {
                const int kb = ks * 32;
                uint32_t ah[4], al[4], bhf[4], blf[4];
                LDSM_X4(ah,  ab + (uint32_t)(a_row * SN_SR + kb + a_colb));
                LDSM_X4(al,  ab + SN_ACH + (uint32_t)(a_row * SN_SR + kb + a_colb));
                LDSM_X4(bhf, wb + (uint32_t)(b_row * SN_SR + kb + b_colb));
                LDSM_X4(blf, wb + SN_WCH + (uint32_t)(b_row * SN_SR + kb + b_colb));
#pragma unroll
                for (int n8 = 0; n8 < 2; n8++) {
                    MMA16816(acc[n8], ah, bhf[n8 * 2], bhf[n8 * 2 + 1]);
                    MMA16816(acc[n8], ah, blf[n8 * 2], blf[n8 * 2 + 1]);
                    MMA16816(acc[n8], al, bhf[n8 * 2], bhf[n8 * 2 + 1]);
                }
            }
            __syncthreads();
        }

        // epilogue: acc -> smem gate buffer [64][52]
        {
            const int row0 = wm * 16 + (lid >> 2);
#pragma unroll
            for (int n8 = 0; n8 < 2; n8++) {
                const int col = wn * 16 + n8 * 8 + (lid & 3) * 2;
                *(float2*)&sGp[row0 * 52 + col] = make_float2(acc[n8][0], acc[n8][1]);
                *(float2*)&sGp[(row0 + 8) * 52 + col] = make_float2(acc[n8][2], acc[n8][3]);
            }
        }
        __syncthreads();

        // CTA-local GRU update for units [16c, 16c+16)
#pragma unroll
        for (int it = 0; it < 3; it++) {
            int item = tid + it * SN_THREADS;
            if (item < 1024) {
                int b = item >> 4, u = item & 15;
                int j = 16 * c + u;
                float gr = sGp[b * 52 + 3 * u];
                float gz = sGp[b * 52 + 3 * u + 1];
                float gn = sGp[b * 52 + 3 * u + 2];
                float xr = sXg[(b * 3 + 0) * 16 + u];
                float xz = sXg[(b * 3 + 1) * 16 + u];
                float xn = sXg[(b * 3 + 2) * 16 + u];
                float rr = fast_sigmoid(xr + gr + sBh[3 * u]);
                float zz = fast_sigmoid(xz + gz + sBh[3 * u + 1]);
                float nn = fast_tanh(xn + rr * (gn + sBh[3 * u + 2]));
                float hnew = (1.0f - zz) * nn + zz * ph[it];
                size_t row = (size_t)b * T_ + t;
                g_h[nxt][b * H_ + j] = hnew;
                hout[row * H_ + j] = hnew;
                __nv_bfloat16 hh = __float2bfloat16_rn(hnew);
                __nv_bfloat16 hl = __float2bfloat16_rn(hnew - __bfloat162float(hh));
                g_hhi[nxt][b * H_ + j] = hh;
                g_hlo[nxt][b * H_ + j] = hl;
                ahi[row * H_ + j] = hh;
                alo[row * H_ + j] = hl;
                if (t == T_ - 1) state_out[b * H_ + j] = hnew;
            }
        }
        grid_barrier64(c);         // single barrier per step
    }
}

// ---------------- launch ----------------
extern "C" void kernel_launch(void* const* d_in, const int* in_sizes, int n_in,
                              void* d_out, int out_size)
{
    const void*  x   = d_in[0];
    const float* emb = (const float*)d_in[1];
    const float* Wx0 = (const float*)d_in[2];
    const float* Wh0 = (const float*)d_in[3];
    const float* bx0 = (const float*)d_in[4];
    const float* bh0 = (const float*)d_in[5];
    const float* Wx  = (const float*)d_in[6];
    const float* Wh  = (const float*)d_in[7];
    const float* bx  = (const float*)d_in[8];
    const float* bh  = (const float*)d_in[9];

    float* out     = (float*)d_out;
    float* enc_out = out;
    float* states  = out + (size_t)M_ * H_;
    float* mask    = states + (size_t)4 * B_ * H_;

    void *p_xg, *p_b0, *p_ahi, *p_alo, *p_whi, *p_wlo, *p_whh, *p_whl;
    cudaGetSymbolAddress(&p_xg,  g_xg);
    cudaGetSymbolAddress(&p_b0,  g_buf0);
    cudaGetSymbolAddress(&p_ahi, g_ahi);
    cudaGetSymbolAddress(&p_alo, g_alo);
    cudaGetSymbolAddress(&p_whi, g_wthi);
    cudaGetSymbolAddress(&p_wlo, g_wtlo);
    cudaGetSymbolAddress(&p_whh, g_whthi);
    cudaGetSymbolAddress(&p_whl, g_whtlo);
    float* xg  = (float*)p_xg;
    float* b0  = (float*)p_b0;
    __nv_bfloat16* ahi = (__nv_bfloat16*)p_ahi;
    __nv_bfloat16* alo = (__nv_bfloat16*)p_alo;
    __nv_bfloat16* whi = (__nv_bfloat16*)p_whi;
    __nv_bfloat16* wlo = (__nv_bfloat16*)p_wlo;
    __nv_bfloat16* whh = (__nv_bfloat16*)p_whh;
    __nv_bfloat16* whl = (__nv_bfloat16*)p_whl;

    cudaFuncSetAttribute(scan_mma_kernel, cudaFuncAttributeMaxDynamicSharedMemorySize,
                         SN_SMEM);
    cudaFuncSetAttribute(gemm_mma_kernel, cudaFuncAttributeMaxDynamicSharedMemorySize,
                         GT_SMEM);

    detect_kernel<<<1, 64>>>((const int*)x);
    embed_kernel<<<M_, 128>>>(x, emb, ahi, alo, mask);

    // layer 0: E=512 -> H
    convertWT_kernel<<<dim3(G3_ / 32, E_ / 32), 256>>>(Wx0, whi, wlo, E_);
    gemm_mma_kernel<<<dim3(G3_ / 128, M_ / 128), 256, GT_SMEM>>>(
        ahi, alo, whi, wlo, bx0, xg, E_);
    convertWT_kernel<<<dim3(G3_ / 32, H_ / 32), 256>>>(Wh0, whh, whl, H_);
    scan_mma_kernel<<<SN_CTAS, SN_THREADS, SN_SMEM>>>(
        xg, whh, whl, bh0, b0, ahi, alo, states);

    // layers 1..3: H -> H
    for (int l = 0; l < 3; l++) {
        float* out_act = (l == 2) ? enc_out : b0;
        convertWT_kernel<<<dim3(G3_ / 32, H_ / 32), 256>>>(
            Wx + (size_t)l * H_ * G3_, whi, wlo, H_);
        gemm_mma_kernel<<<dim3(G3_ / 128, M_ / 128), 256, GT_SMEM>>>(
            ahi, alo, whi, wlo, bx + (size_t)l * G3_, xg, H_);
        convertWT_kernel<<<dim3(G3_ / 32, H_ / 32), 256>>>(
            Wh + (size_t)l * H_ * G3_, whh, whl, H_);
        scan_mma_kernel<<<SN_CTAS, SN_THREADS, SN_SMEM>>>(
            xg, whh, whl, bh + (size_t)l * G3_,
            out_act, ahi, alo, states + (size_t)(l + 1) * B_ * H_);
    }
}

// round 13
// speedup vs baseline: 1.2081x; 1.2081x over previous
#include <cuda_runtime.h>
#include <cuda_bf16.h>
#include <cstdint>
#include <cmath>

#define B_  64
#define T_  512
#define E_  512
#define H_  1024
#define M_  (B_*T_)     // 32768 rows
#define G3_ (3*H_)      // 3072

extern __shared__ char hx_smem[];

// ---------------- scratch ----------------
__device__ float g_xg [(size_t)M_ * G3_];                // permuted xg: [t][cta][b][48]
__device__ float g_h[2][B_ * H_];
__device__ __nv_bfloat16 g_hc_hi[2 * 8 * B_ * 136];      // h chunk-major [par][ck][b][136]
__device__ __nv_bfloat16 g_hc_lo[2 * 8 * B_ * 136];
__device__ __nv_bfloat16 g_ahi[(size_t)M_ * H_];
__device__ __nv_bfloat16 g_alo[(size_t)M_ * H_];
__device__ __nv_bfloat16 g_wthi[(size_t)G3_ * H_];       // Wx^T [N][K]
__device__ __nv_bfloat16 g_wtlo[(size_t)G3_ * H_];
__device__ __nv_bfloat16 g_wchi[64 * 8 * 48 * 136];      // Wh per-(cta,ck) blocks
__device__ __nv_bfloat16 g_wclo[64 * 8 * 48 * 136];
__device__ unsigned g_grp_cnt[8];
__device__ unsigned g_root_cnt = 0;
__device__ unsigned g_bar_gen  = 0;
__device__ int g_x_is_i64 = 1;

// ---------------- helpers ----------------
__device__ __forceinline__ float fast_tanh(float x) {
    float y; asm("tanh.approx.f32 %0, %1;" : "=f"(y) : "f"(x)); return y;
}
__device__ __forceinline__ float fast_sigmoid(float x) {
    return 0.5f * fast_tanh(0.5f * x) + 0.5f;
}
__device__ __forceinline__ uint32_t smem_u32(const void* p) {
    return (uint32_t)__cvta_generic_to_shared(p);
}
__device__ __forceinline__ void cp_async16(uint32_t smem_addr, const void* gptr) {
    asm volatile("cp.async.cg.shared.global [%0], [%1], 16;"
                 :: "r"(smem_addr), "l"(gptr));
}
__device__ __forceinline__ void cp_commit() { asm volatile("cp.async.commit_group;"); }
__device__ __forceinline__ void cp_wait0() { asm volatile("cp.async.wait_group 0;"); }
__device__ __forceinline__ void cp_wait1() { asm volatile("cp.async.wait_group 1;"); }

// sm_90 bulk async copy: ONE instruction per tile, completion via mbarrier tx-bytes
__device__ __forceinline__ void bulk_g2s(uint32_t dst, const void* src,
                                         uint32_t bytes, uint32_t mbar) {
    asm volatile(
        "cp.async.bulk.shared::cluster.global.mbarrier::complete_tx::bytes "
        "[%0], [%1], %2, [%3];"
        :: "r"(dst), "l"(src), "r"(bytes), "r"(mbar) : "memory");
}
#define MBAR_INIT(addr, cnt) \
    asm volatile("mbarrier.init.shared.b64 [%0], %1;" :: "r"(addr), "r"(cnt) : "memory")
#define MBAR_EXPECT(addr, bytes) \
    asm volatile("mbarrier.arrive.expect_tx.shared.b64 _, [%0], %1;" \
                 :: "r"(addr), "r"(bytes) : "memory")
#define MBAR_WAIT(addr, parity) do {                                             \
    asm volatile("{\n\t.reg .pred P1;\n\t"                                       \
        "WAIT_%=:\n\t"                                                           \
        "mbarrier.try_wait.parity.acquire.cta.shared::cta.b64 P1, [%0], %1, 0x989680;\n\t" \
        "@P1 bra.uni DONE_%=;\n\t"                                               \
        "bra.uni WAIT_%=;\n\t"                                                   \
        "DONE_%=:\n\t}"                                                          \
        :: "r"(addr), "r"(parity) : "memory");                                   \
} while (0)

#define LDSM_X4(r, addr) \
    asm volatile("ldmatrix.sync.aligned.m8n8.x4.shared.b16 {%0,%1,%2,%3}, [%4];" \
        : "=r"((r)[0]), "=r"((r)[1]), "=r"((r)[2]), "=r"((r)[3]) : "r"(addr))

#define MMA16816(d, a, b0, b1) \
    asm volatile("mma.sync.aligned.m16n8k16.row.col.f32.bf16.bf16.f32 " \
        "{%0,%1,%2,%3}, {%4,%5,%6,%7}, {%8,%9}, {%0,%1,%2,%3};" \
        : "+f"((d)[0]), "+f"((d)[1]), "+f"((d)[2]), "+f"((d)[3]) \
        : "r"((a)[0]), "r"((a)[1]), "r"((a)[2]), "r"((a)[3]), "r"(b0), "r"(b1))

// ---------------- int64-vs-int32 detection ----------------
__global__ void detect_kernel(const int* __restrict__ x32) {
    __shared__ int nz;
    if (threadIdx.x == 0) nz = 0;
    __syncthreads();
    if (x32[2 * threadIdx.x + 1] != 0) atomicExch(&nz, 1);
    __syncthreads();
    if (threadIdx.x == 0) g_x_is_i64 = (nz == 0) ? 1 : 0;
}

// ---------------- embedding gather (bf16 hi/lo) + pad mask ----------------
__global__ __launch_bounds__(128) void embed_kernel(
    const void* __restrict__ xraw, const float* __restrict__ emb,
    __nv_bfloat16* __restrict__ ahi, __nv_bfloat16* __restrict__ alo,
    float* __restrict__ mask_out)
{
    const int r = blockIdx.x;
    long long idx;
    if (g_x_is_i64) idx = ((const long long*)xraw)[r];
    else            idx = (long long)((const int*)xraw)[r];
    float4 v = ((const float4*)(emb + (size_t)idx * E_))[threadIdx.x];
    union { __nv_bfloat16 b[4]; uint2 u; } Hh, Ll;
    float f[4] = {v.x, v.y, v.z, v.w};
#pragma unroll
    for (int q = 0; q < 4; q++) {
        __nv_bfloat16 h = __float2bfloat16_rn(f[q]);
        Hh.b[q] = h;
        Ll.b[q] = __float2bfloat16_rn(f[q] - __bfloat162float(h));
    }
    ((uint2*)(ahi + (size_t)r * E_))[threadIdx.x] = Hh.u;
    ((uint2*)(alo + (size_t)r * E_))[threadIdx.x] = Ll.u;
    if (threadIdx.x == 0) mask_out[r] = (idx != 0) ? 1.0f : 0.0f;
}

// ---------------- W [K][3072] fp32 -> W^T [3072][K] bf16 hi/lo (Wx path) ----------------
__global__ __launch_bounds__(256) void convertWT_kernel(
    const float* __restrict__ W, __nv_bfloat16* __restrict__ Thi,
    __nv_bfloat16* __restrict__ Tlo, int K)
{
    __shared__ float t[32][33];
    const int n0 = blockIdx.x * 32, k0 = blockIdx.y * 32;
    const int tx = threadIdx.x & 31, ty = threadIdx.x >> 5;
#pragma unroll
    for (int i = 0; i < 32; i += 8)
        t[ty + i][tx] = W[(size_t)(k0 + ty + i) * G3_ + n0 + tx];
    __syncthreads();
#pragma unroll
    for (int i = 0; i < 32; i += 8) {
        float v = t[tx][ty + i];
        __nv_bfloat16 h = __float2bfloat16_rn(v);
        size_t o = (size_t)(n0 + ty + i) * K + k0 + tx;
        Thi[o] = h;
        Tlo[o] = __float2bfloat16_rn(v - __bfloat162float(h));
    }
}

// ---------------- Wh -> per-(cta,ck) permuted contiguous blocks [48][136] ----------------
__global__ __launch_bounds__(256) void convertWhc_kernel(
    const float* __restrict__ Wh, __nv_bfloat16* __restrict__ wchi,
    __nv_bfloat16* __restrict__ wclo)
{
    __shared__ float tbuf[128][49];
    const int c = blockIdx.x >> 3, ck = blockIdx.x & 7;
    for (int i = threadIdx.x; i < 128 * 48; i += 256) {
        int k = i / 48, col = i % 48;
        int g = col >> 4, u = col & 15;
        tbuf[k][3 * u + g] = Wh[(size_t)(ck * 128 + k) * G3_ + g * H_ + 16 * c + u];
    }
    __syncthreads();
    size_t base = (size_t)blockIdx.x * 48 * 136;
    for (int i = threadIdx.x; i < 48 * 136; i += 256) {
        int q = i / 136, kk = i % 136;
        float v = (kk < 128) ? tbuf[kk][q] : 0.0f;
        __nv_bfloat16 h = __float2bfloat16_rn(v);
        wchi[base + i] = h;
        wclo[base + i] = __float2bfloat16_rn(v - __bfloat162float(h));
    }
}

// ---------------- bf16-split mma.sync GEMM -> permuted xg (+bias) -------
#define GT_TILE   18432                // 128 * 144
#define GT_STAGE  (4 * GT_TILE)
#define GT_SMEM   (2 * GT_STAGE)       // 147456 B

__global__ __launch_bounds__(256, 1) void gemm_mma_kernel(
    const __nv_bfloat16* __restrict__ Ahi, const __nv_bfloat16* __restrict__ Alo,
    const __nv_bfloat16* __restrict__ Bhi, const __nv_bfloat16* __restrict__ Blo,
    const float* __restrict__ bias, float* __restrict__ xgp, int K)
{
    const uint32_t sb = smem_u32(hx_smem);
    const int tid = threadIdx.x;
    const int wid = tid >> 5, lid = tid & 31;
    const int wm = wid & 1, wn = wid >> 1;
    const int n0 = blockIdx.x * 128, m0 = blockIdx.y * 128;
    const int nch = K >> 6;

    float acc[4][4][4];
#pragma unroll
    for (int mf = 0; mf < 4; mf++)
#pragma unroll
        for (int n8 = 0; n8 < 4; n8++)
#pragma unroll
            for (int q = 0; q < 4; q++) acc[mf][n8][q] = 0.0f;

    auto stage = [&](int kc) {
        const uint32_t st = sb + (uint32_t)(kc & 1) * GT_STAGE;
        const int koff = kc * 64;
#pragma unroll
        for (int q = 0; q < 4; q++) {
            int i = tid + 256 * q;
            int row = i >> 3, seg = i & 7;
            uint32_t d = st + (uint32_t)(row * 144 + seg * 16);
            size_t ao = (size_t)(m0 + row) * K + koff + seg * 8;
            size_t bo = (size_t)(n0 + row) * K + koff + seg * 8;
            cp_async16(d,               Ahi + ao);
            cp_async16(d + GT_TILE,     Alo + ao);
            cp_async16(d + 2 * GT_TILE, Bhi + bo);
            cp_async16(d + 3 * GT_TILE, Blo + bo);
        }
        cp_commit();
    };

    const int a_row = wm * 64 + (lid & 15);
    const int a_colb = (lid >> 4) * 16;
    const int b_row = wn * 32 + ((lid >> 4) << 3) + (lid & 7);
    const int b_colb = ((lid >> 3) & 1) * 16;

    stage(0);
    for (int c = 0; c < nch; c++) {
        if (c + 1 < nch) { stage(c + 1); cp_wait1(); }
        else             { cp_wait0(); }
        __syncthreads();

        const uint32_t st = sb + (uint32_t)(c & 1) * GT_STAGE;
#pragma unroll
        for (int ks = 0; ks < 4; ks++) {
            const int kb = ks * 32;
            uint32_t ah[4][4], al[4][4], bh[2][4], bl[2][4];
#pragma unroll
            for (int mf = 0; mf < 4; mf++) {
                uint32_t addr = st + (uint32_t)((a_row + mf * 16) * 144 + kb + a_colb);
                LDSM_X4(ah[mf], addr);
                LDSM_X4(al[mf], addr + GT_TILE);
            }
#pragma unroll
            for (int nf = 0; nf < 2; nf++) {
                uint32_t addr = st + 2 * GT_TILE +
                                (uint32_t)((b_row + nf * 16) * 144 + kb + b_colb);
                LDSM_X4(bh[nf], addr);
                LDSM_X4(bl[nf], addr + GT_TILE);
            }
#pragma unroll
            for (int mf = 0; mf < 4; mf++)
#pragma unroll
                for (int n8 = 0; n8 < 4; n8++) {
                    const int nf = n8 >> 1, hh = (n8 & 1) * 2;
                    MMA16816(acc[mf][n8], ah[mf], bh[nf][hh], bh[nf][hh + 1]);
                    MMA16816(acc[mf][n8], ah[mf], bl[nf][hh], bl[nf][hh + 1]);
                    MMA16816(acc[mf][n8], al[mf], bh[nf][hh], bh[nf][hh + 1]);
                }
        }
        __syncthreads();
    }

    // epilogue: scatter bias-added scalars into permuted xg [t][cta][b][48]
    auto pstore = [&](int t, int b, int n, float v) {
        int g = n >> 10, j = n & 1023;
        xgp[(((size_t)t * 64 + (j >> 4)) * 64 + b) * 48 + 3 * (j & 15) + g] = v;
    };
#pragma unroll
    for (int mf = 0; mf < 4; mf++) {
        const int gm = m0 + wm * 64 + mf * 16 + (lid >> 2);
        const int b0r = gm >> 9, t0r = gm & 511;
        const int b1r = (gm + 8) >> 9, t1r = (gm + 8) & 511;
#pragma unroll
        for (int n8 = 0; n8 < 4; n8++) {
            const int gc = n0 + wn * 32 + n8 * 8 + (lid & 3) * 2;
            float bb0 = bias[gc], bb1 = bias[gc + 1];
            pstore(t0r, b0r, gc,     acc[mf][n8][0] + bb0);
            pstore(t0r, b0r, gc + 1, acc[mf][n8][1] + bb1);
            pstore(t1r, b1r, gc,     acc[mf][n8][2] + bb0);
            pstore(t1r, b1r, gc + 1, acc[mf][n8][3] + bb1);
        }
    }
}

// ---------------- bulk-staged tensor-core scan, one barrier per step --------
#define SN_CTAS    64
#define SN_THREADS 384
#define SB_MB   0
#define SB_W    16
#define SB_WSL  26112                   // per slot: hi 13056 + lo 13056
#define SB_A    (SB_W + 2 * SB_WSL)     // 52240
#define SB_ASL  34816                   // hi 17408 + lo 17408
#define SB_XG   (SB_A + 2 * SB_ASL)     // 121872
#define SB_GP   (SB_XG + 12288)         // 134160
#define SB_BH   (SB_GP + 13312)         // 147472
#define SB_TOT  (SB_BH + 192)           // 147664

__device__ __forceinline__ void grid_barrier64(int c) {
    __syncthreads();
    if (threadIdx.x == 0) {
        __threadfence();
        unsigned gen = *(volatile unsigned*)&g_bar_gen;
        int grp = c & 7;
        if (atomicAdd(&g_grp_cnt[grp], 1u) == 7u) {
            if (atomicAdd(&g_root_cnt, 1u) == 7u) {
                atomicExch(&g_root_cnt, 0u);
#pragma unroll
                for (int i = 0; i < 8; i++) atomicExch(&g_grp_cnt[i], 0u);
                __threadfence();
                atomicAdd(&g_bar_gen, 1u);
            }
        }
        while (*(volatile unsigned*)&g_bar_gen == gen) { }
        __threadfence();
    }
    __syncthreads();
}

__global__ __launch_bounds__(SN_THREADS, 1) void scan_bulk_kernel(
    const float* __restrict__ xgp,
    const __nv_bfloat16* __restrict__ wchi, const __nv_bfloat16* __restrict__ wclo,
    const float* __restrict__ bh, float* __restrict__ hout, int write_hout,
    __nv_bfloat16* __restrict__ ahi, __nv_bfloat16* __restrict__ alo,
    float* __restrict__ state_out,
    __nv_bfloat16* __restrict__ hchi, __nv_bfloat16* __restrict__ hclo)
{
    const uint32_t sb = smem_u32(hx_smem);
    float* sXg = (float*)(hx_smem + SB_XG);
    float* sGp = (float*)(hx_smem + SB_GP);
    float* sBh = (float*)(hx_smem + SB_BH);
    const int c = blockIdx.x, tid = threadIdx.x;
    const int wid = tid >> 5, lid = tid & 31;
    const int wm = wid & 3, wn = wid >> 2;          // 4m x 3n warps

    if (tid == 0) { MBAR_INIT(sb + SB_MB, 1); MBAR_INIT(sb + SB_MB + 8, 1); }
    if (tid < 48) sBh[tid] = bh[(tid % 3) * H_ + 16 * c + tid / 3];
    for (int e = c * SN_THREADS + tid; e < B_ * H_; e += SN_CTAS * SN_THREADS)
        g_h[0][e] = 0.0f;
    for (int e = c * SN_THREADS + tid; e < 8 * B_ * 136; e += SN_CTAS * SN_THREADS) {
        hchi[e] = __float2bfloat16(0.0f);
        hclo[e] = __float2bfloat16(0.0f);
    }
    grid_barrier64(c);

    int ph0 = 0, ph1 = 0;
    const int a_row  = wm * 16 + (lid & 15);
    const int a_colb = (lid >> 4) * 16;
    const int b_row  = wn * 16 + ((lid >> 4) << 3) + (lid & 7);
    const int b_colb = ((lid >> 3) & 1) * 16;

    for (int t = 0; t < T_; t++) {
        const int par = t & 1, nxt = par ^ 1;

        // prefetch old h into registers (fp32 path)
        float ph[3];
#pragma unroll
        for (int it = 0; it < 3; it++) {
            int item = tid + it * SN_THREADS;
            if (item < 1024)
                ph[it] = g_h[par][(item >> 4) * H_ + 16 * c + (item & 15)];
        }

        // issue chunk 0 (+ xg) — 5 bulk copies
        if (tid == 0) {
            MBAR_EXPECT(sb + SB_MB, 73216u);
            size_t wbase = (size_t)(c * 8) * 48 * 136;
            size_t abase = (size_t)(par * 8) * B_ * 136;
            bulk_g2s(sb + SB_W,               wchi + wbase, 13056u, sb + SB_MB);
            bulk_g2s(sb + SB_W + 13056,       wclo + wbase, 13056u, sb + SB_MB);
            bulk_g2s(sb + SB_A,               hchi + abase, 17408u, sb + SB_MB);
            bulk_g2s(sb + SB_A + 17408,       hclo + abase, 17408u, sb + SB_MB);
            bulk_g2s(sb + SB_XG,
                     xgp + ((size_t)t * 64 + c) * 64 * 48, 12288u, sb + SB_MB);
        }

        float acc[2][4];
#pragma unroll
        for (int n8 = 0; n8 < 2; n8++)
#pragma unroll
            for (int q = 0; q < 4; q++) acc[n8][q] = 0.0f;

        for (int ck = 0; ck < 8; ck++) {
            const int s0 = ck & 1;
            if (ck + 1 < 8 && tid == 0) {
                const int s1 = s0 ^ 1;
                const uint32_t mb1 = sb + SB_MB + 8 * s1;
                MBAR_EXPECT(mb1, 60928u);
                size_t wbase = (size_t)(c * 8 + ck + 1) * 48 * 136;
                size_t abase = (size_t)(par * 8 + ck + 1) * B_ * 136;
                bulk_g2s(sb + SB_W + s1 * SB_WSL,           wchi + wbase, 13056u, mb1);
                bulk_g2s(sb + SB_W + s1 * SB_WSL + 13056,   wclo + wbase, 13056u, mb1);
                bulk_g2s(sb + SB_A + s1 * SB_ASL,           hchi + abase, 17408u, mb1);
                bulk_g2s(sb + SB_A + s1 * SB_ASL + 17408,   hclo + abase, 17408u, mb1);
            }
            const uint32_t mb0 = sb + SB_MB + 8 * s0;
            if (s0 == 0) { MBAR_WAIT(mb0, ph0); ph0 ^= 1; }
            else         { MBAR_WAIT(mb0, ph1); ph1 ^= 1; }

            const uint32_t wb = sb + SB_W + s0 * SB_WSL;
            const uint32_t ab = sb + SB_A + s0 * SB_ASL;
#pragma unroll
            for (int ks = 0; ks < 8; ks++) {
                const int kb = ks * 32;
                uint32_t ah[4], al[4], bhf[4], blf[4];
                LDSM_X4(ah,  ab + (uint32_t)(a_row * 272 + kb + a_colb));
                LDSM_X4(al,  ab + 17408 + (uint32_t)(a_row * 272 + kb + a_colb));
                LDSM_X4(bhf, wb + (uint32_t)(b_row * 272 + kb + b_colb));
                LDSM_X4(blf, wb + 13056 + (uint32_t)(b_row * 272 + kb + b_colb));
#pragma unroll
                for (int n8 = 0; n8 < 2; n8++) {
                    MMA16816(acc[n8], ah, bhf[n8 * 2], bhf[n8 * 2 + 1]);
                    MMA16816(acc[n8], ah, blf[n8 * 2], blf[n8 * 2 + 1]);
                    MMA16816(acc[n8], al, bhf[n8 * 2], bhf[n8 * 2 + 1]);
                }
            }
            __syncthreads();          // protect slot reuse
        }

        // epilogue: acc -> smem gate buffer [64][52]
        {
            const int row0 = wm * 16 + (lid >> 2);
#pragma unroll
            for (int n8 = 0; n8 < 2; n8++) {
                const int col = wn * 16 + n8 * 8 + (lid & 3) * 2;
                *(float2*)&sGp[row0 * 52 + col] = make_float2(acc[n8][0], acc[n8][1]);
                *(float2*)&sGp[(row0 + 8) * 52 + col] = make_float2(acc[n8][2], acc[n8][3]);
            }
        }
        __syncthreads();

        // CTA-local GRU update for units [16c, 16c+16)
#pragma unroll
        for (int it = 0; it < 3; it++) {
            int item = tid + it * SN_THREADS;
            if (item < 1024) {
                int b = item >> 4, u = item & 15;
                int j = 16 * c + u;
                float gr = sGp[b * 52 + 3 * u];
                float gz = sGp[b * 52 + 3 * u + 1];
                float gn = sGp[b * 52 + 3 * u + 2];
                float xr = sXg[b * 48 + 3 * u];
                float xz = sXg[b * 48 + 3 * u + 1];
                float xn = sXg[b * 48 + 3 * u + 2];
                float rr = fast_sigmoid(xr + gr + sBh[3 * u]);
                float zz = fast_sigmoid(xz + gz + sBh[3 * u + 1]);
                float nn = fast_tanh(xn + rr * (gn + sBh[3 * u + 2]));
                float hnew = (1.0f - zz) * nn + zz * ph[it];
                size_t row = (size_t)b * T_ + t;
                g_h[nxt][b * H_ + j] = hnew;
                if (write_hout) hout[row * H_ + j] = hnew;
                __nv_bfloat16 hh = __float2bfloat16_rn(hnew);
                __nv_bfloat16 hl = __float2bfloat16_rn(hnew - __bfloat162float(hh));
                int ck2 = j >> 7, kk = j & 127;
                hchi[((size_t)(nxt * 8 + ck2) * B_ + b) * 136 + kk] = hh;
                hclo[((size_t)(nxt * 8 + ck2) * B_ + b) * 136 + kk] = hl;
                ahi[row * H_ + j] = hh;
                alo[row * H_ + j] = hl;
                if (t == T_ - 1) state_out[b * H_ + j] = hnew;
            }
        }
        grid_barrier64(c);
    }
}

// ---------------- launch ----------------
extern "C" void kernel_launch(void* const* d_in, const int* in_sizes, int n_in,
                              void* d_out, int out_size)
{
    const void*  x   = d_in[0];
    const float* emb = (const float*)d_in[1];
    const float* Wx0 = (const float*)d_in[2];
    const float* Wh0 = (const float*)d_in[3];
    const float* bx0 = (const float*)d_in[4];
    const float* bh0 = (const float*)d_in[5];
    const float* Wx  = (const float*)d_in[6];
    const float* Wh  = (const float*)d_in[7];
    const float* bx  = (const float*)d_in[8];
    const float* bh  = (const float*)d_in[9];

    float* out     = (float*)d_out;
    float* enc_out = out;
    float* states  = out + (size_t)M_ * H_;
    float* mask    = states + (size_t)4 * B_ * H_;

    void *p_xg, *p_ahi, *p_alo, *p_whi, *p_wlo, *p_wch, *p_wcl, *p_hch, *p_hcl;
    cudaGetSymbolAddress(&p_xg,  g_xg);
    cudaGetSymbolAddress(&p_ahi, g_ahi);
    cudaGetSymbolAddress(&p_alo, g_alo);
    cudaGetSymbolAddress(&p_whi, g_wthi);
    cudaGetSymbolAddress(&p_wlo, g_wtlo);
    cudaGetSymbolAddress(&p_wch, g_wchi);
    cudaGetSymbolAddress(&p_wcl, g_wclo);
    cudaGetSymbolAddress(&p_hch, g_hc_hi);
    cudaGetSymbolAddress(&p_hcl, g_hc_lo);
    float* xgp = (float*)p_xg;
    __nv_bfloat16* ahi  = (__nv_bfloat16*)p_ahi;
    __nv_bfloat16* alo  = (__nv_bfloat16*)p_alo;
    __nv_bfloat16* whi  = (__nv_bfloat16*)p_whi;
    __nv_bfloat16* wlo  = (__nv_bfloat16*)p_wlo;
    __nv_bfloat16* wchi = (__nv_bfloat16*)p_wch;
    __nv_bfloat16* wclo = (__nv_bfloat16*)p_wcl;
    __nv_bfloat16* hchi = (__nv_bfloat16*)p_hch;
    __nv_bfloat16* hclo = (__nv_bfloat16*)p_hcl;

    cudaFuncSetAttribute(scan_bulk_kernel, cudaFuncAttributeMaxDynamicSharedMemorySize,
                         SB_TOT);
    cudaFuncSetAttribute(gemm_mma_kernel, cudaFuncAttributeMaxDynamicSharedMemorySize,
                         GT_SMEM);

    detect_kernel<<<1, 64>>>((const int*)x);
    embed_kernel<<<M_, 128>>>(x, emb, ahi, alo, mask);

    for (int l = 0; l < 4; l++) {
        const float* WxL = (l == 0) ? Wx0 : Wx + (size_t)(l - 1) * H_ * G3_;
        const float* WhL = (l == 0) ? Wh0 : Wh + (size_t)(l - 1) * H_ * G3_;
        const float* bxL = (l == 0) ? bx0 : bx + (size_t)(l - 1) * G3_;
        const float* bhL = (l == 0) ? bh0 : bh + (size_t)(l - 1) * G3_;
        const int K = (l == 0) ? E_ : H_;

        convertWT_kernel<<<dim3(G3_ / 32, K / 32), 256>>>(WxL, whi, wlo, K);
        gemm_mma_kernel<<<dim3(G3_ / 128, M_ / 128), 256, GT_SMEM>>>(
            ahi, alo, whi, wlo, bxL, xgp, K);
        convertWhc_kernel<<<512, 256>>>(WhL, wchi, wclo);
        scan_bulk_kernel<<<SN_CTAS, SN_THREADS, SB_TOT>>>(
            xgp, wchi, wclo, bhL, enc_out, (l == 3) ? 1 : 0,
            ahi, alo, states + (size_t)l * B_ * H_, hchi, hclo);
    }
}

// round 14
// speedup vs baseline: 1.2314x; 1.0193x over previous
#include <cuda_runtime.h>
#include <cuda_bf16.h>
#include <cstdint>
#include <cmath>

#define B_  64
#define T_  512
#define E_  512
#define H_  1024
#define M_  (B_*T_)     // 32768 rows
#define G3_ (3*H_)      // 3072

extern __shared__ char hx_smem[];

// ---------------- scratch ----------------
__device__ float g_xg [(size_t)M_ * G3_];                // permuted xg: [t][cta][b][48]
__device__ float g_h[2][B_ * H_];
__device__ __nv_bfloat16 g_hc_hi[2 * 8 * B_ * 136];      // h chunk-major [par][ck][b][136]
__device__ __nv_bfloat16 g_hc_lo[2 * 8 * B_ * 136];
__device__ __nv_bfloat16 g_ahi[(size_t)M_ * H_];
__device__ __nv_bfloat16 g_alo[(size_t)M_ * H_];
__device__ __nv_bfloat16 g_wthi[(size_t)G3_ * H_];       // Wx^T [N][K]
__device__ __nv_bfloat16 g_wtlo[(size_t)G3_ * H_];
__device__ __nv_bfloat16 g_wchi[64 * 8 * 48 * 136];      // Wh per-(cta,ck) blocks
__device__ __nv_bfloat16 g_wclo[64 * 8 * 48 * 136];
__device__ unsigned g_grp_cnt[8];
__device__ unsigned g_root_cnt = 0;
__device__ unsigned g_bar_gen  = 0;
__device__ int g_x_is_i64 = 1;

// ---------------- helpers ----------------
__device__ __forceinline__ float fast_tanh(float x) {
    float y; asm("tanh.approx.f32 %0, %1;" : "=f"(y) : "f"(x)); return y;
}
__device__ __forceinline__ float fast_sigmoid(float x) {
    return 0.5f * fast_tanh(0.5f * x) + 0.5f;
}
__device__ __forceinline__ uint32_t smem_u32(const void* p) {
    return (uint32_t)__cvta_generic_to_shared(p);
}
__device__ __forceinline__ void cp_async16(uint32_t smem_addr, const void* gptr) {
    asm volatile("cp.async.cg.shared.global [%0], [%1], 16;"
                 :: "r"(smem_addr), "l"(gptr));
}
__device__ __forceinline__ void cp_commit() { asm volatile("cp.async.commit_group;"); }
__device__ __forceinline__ void cp_wait0() { asm volatile("cp.async.wait_group 0;"); }
__device__ __forceinline__ void cp_wait1() { asm volatile("cp.async.wait_group 1;"); }

// sm_90 bulk async copy: ONE instruction per tile, completion via mbarrier tx-bytes
__device__ __forceinline__ void bulk_g2s(uint32_t dst, const void* src,
                                         uint32_t bytes, uint32_t mbar) {
    asm volatile(
        "cp.async.bulk.shared::cluster.global.mbarrier::complete_tx::bytes "
        "[%0], [%1], %2, [%3];"
        :: "r"(dst), "l"(src), "r"(bytes), "r"(mbar) : "memory");
}
#define MBAR_INIT(addr, cnt) \
    asm volatile("mbarrier.init.shared.b64 [%0], %1;" :: "r"(addr), "r"(cnt) : "memory")
#define MBAR_EXPECT(addr, bytes) \
    asm volatile("mbarrier.arrive.expect_tx.shared.b64 _, [%0], %1;" \
                 :: "r"(addr), "r"(bytes) : "memory")
#define MBAR_WAIT(addr, parity) do {                                             \
    asm volatile("{\n\t.reg .pred P1;\n\t"                                       \
        "WAIT_%=:\n\t"                                                           \
        "mbarrier.try_wait.parity.acquire.cta.shared::cta.b64 P1, [%0], %1, 0x989680;\n\t" \
        "@P1 bra.uni DONE_%=;\n\t"                                               \
        "bra.uni WAIT_%=;\n\t"                                                   \
        "DONE_%=:\n\t}"                                                          \
        :: "r"(addr), "r"(parity) : "memory");                                   \
} while (0)

#define LDSM_X4(r, addr) \
    asm volatile("ldmatrix.sync.aligned.m8n8.x4.shared.b16 {%0,%1,%2,%3}, [%4];" \
        : "=r"((r)[0]), "=r"((r)[1]), "=r"((r)[2]), "=r"((r)[3]) : "r"(addr))

#define MMA16816(d, a, b0, b1) \
    asm volatile("mma.sync.aligned.m16n8k16.row.col.f32.bf16.bf16.f32 " \
        "{%0,%1,%2,%3}, {%4,%5,%6,%7}, {%8,%9}, {%0,%1,%2,%3};" \
        : "+f"((d)[0]), "+f"((d)[1]), "+f"((d)[2]), "+f"((d)[3]) \
        : "r"((a)[0]), "r"((a)[1]), "r"((a)[2]), "r"((a)[3]), "r"(b0), "r"(b1))

// ---------------- int64-vs-int32 detection ----------------
__global__ void detect_kernel(const int* __restrict__ x32) {
    __shared__ int nz;
    if (threadIdx.x == 0) nz = 0;
    __syncthreads();
    if (x32[2 * threadIdx.x + 1] != 0) atomicExch(&nz, 1);
    __syncthreads();
    if (threadIdx.x == 0) g_x_is_i64 = (nz == 0) ? 1 : 0;
}

// ---------------- embedding gather (bf16 hi/lo) + pad mask ----------------
__global__ __launch_bounds__(128) void embed_kernel(
    const void* __restrict__ xraw, const float* __restrict__ emb,
    __nv_bfloat16* __restrict__ ahi, __nv_bfloat16* __restrict__ alo,
    float* __restrict__ mask_out)
{
    const int r = blockIdx.x;
    long long idx;
    if (g_x_is_i64) idx = ((const long long*)xraw)[r];
    else            idx = (long long)((const int*)xraw)[r];
    float4 v = ((const float4*)(emb + (size_t)idx * E_))[threadIdx.x];
    union { __nv_bfloat16 b[4]; uint2 u; } Hh, Ll;
    float f[4] = {v.x, v.y, v.z, v.w};
#pragma unroll
    for (int q = 0; q < 4; q++) {
        __nv_bfloat16 h = __float2bfloat16_rn(f[q]);
        Hh.b[q] = h;
        Ll.b[q] = __float2bfloat16_rn(f[q] - __bfloat162float(h));
    }
    ((uint2*)(ahi + (size_t)r * E_))[threadIdx.x] = Hh.u;
    ((uint2*)(alo + (size_t)r * E_))[threadIdx.x] = Ll.u;
    if (threadIdx.x == 0) mask_out[r] = (idx != 0) ? 1.0f : 0.0f;
}

// ---------------- W [K][3072] fp32 -> W^T [3072][K] bf16 hi/lo (Wx path) ----------------
__global__ __launch_bounds__(256) void convertWT_kernel(
    const float* __restrict__ W, __nv_bfloat16* __restrict__ Thi,
    __nv_bfloat16* __restrict__ Tlo, int K)
{
    __shared__ float t[32][33];
    const int n0 = blockIdx.x * 32, k0 = blockIdx.y * 32;
    const int tx = threadIdx.x & 31, ty = threadIdx.x >> 5;
#pragma unroll
    for (int i = 0; i < 32; i += 8)
        t[ty + i][tx] = W[(size_t)(k0 + ty + i) * G3_ + n0 + tx];
    __syncthreads();
#pragma unroll
    for (int i = 0; i < 32; i += 8) {
        float v = t[tx][ty + i];
        __nv_bfloat16 h = __float2bfloat16_rn(v);
        size_t o = (size_t)(n0 + ty + i) * K + k0 + tx;
        Thi[o] = h;
        Tlo[o] = __float2bfloat16_rn(v - __bfloat162float(h));
    }
}

// ---------------- Wh -> per-(cta,ck) permuted contiguous blocks [48][136] ----------------
__global__ __launch_bounds__(256) void convertWhc_kernel(
    const float* __restrict__ Wh, __nv_bfloat16* __restrict__ wchi,
    __nv_bfloat16* __restrict__ wclo)
{
    __shared__ float tbuf[128][49];
    const int c = blockIdx.x >> 3, ck = blockIdx.x & 7;
    for (int i = threadIdx.x; i < 128 * 48; i += 256) {
        int k = i / 48, col = i % 48;
        int g = col >> 4, u = col & 15;
        tbuf[k][3 * u + g] = Wh[(size_t)(ck * 128 + k) * G3_ + g * H_ + 16 * c + u];
    }
    __syncthreads();
    size_t base = (size_t)blockIdx.x * 48 * 136;
    for (int i = threadIdx.x; i < 48 * 136; i += 256) {
        int q = i / 136, kk = i % 136;
        float v = (kk < 128) ? tbuf[kk][q] : 0.0f;
        __nv_bfloat16 h = __float2bfloat16_rn(v);
        wchi[base + i] = h;
        wclo[base + i] = __float2bfloat16_rn(v - __bfloat162float(h));
    }
}

// ---------------- bf16-split mma.sync GEMM -> permuted xg (+bias) -------
#define GT_TILE   18432                // 128 * 144
#define GT_STAGE  (4 * GT_TILE)
#define GT_SMEM   (2 * GT_STAGE)       // 147456 B

__global__ __launch_bounds__(256, 1) void gemm_mma_kernel(
    const __nv_bfloat16* __restrict__ Ahi, const __nv_bfloat16* __restrict__ Alo,
    const __nv_bfloat16* __restrict__ Bhi, const __nv_bfloat16* __restrict__ Blo,
    const float* __restrict__ bias, float* __restrict__ xgp, int K)
{
    const uint32_t sb = smem_u32(hx_smem);
    const int tid = threadIdx.x;
    const int wid = tid >> 5, lid = tid & 31;
    const int wm = wid & 1, wn = wid >> 1;
    const int n0 = blockIdx.x * 128, m0 = blockIdx.y * 128;
    const int nch = K >> 6;

    float acc[4][4][4];
#pragma unroll
    for (int mf = 0; mf < 4; mf++)
#pragma unroll
        for (int n8 = 0; n8 < 4; n8++)
#pragma unroll
            for (int q = 0; q < 4; q++) acc[mf][n8][q] = 0.0f;

    auto stage = [&](int kc) {
        const uint32_t st = sb + (uint32_t)(kc & 1) * GT_STAGE;
        const int koff = kc * 64;
#pragma unroll
        for (int q = 0; q < 4; q++) {
            int i = tid + 256 * q;
            int row = i >> 3, seg = i & 7;
            uint32_t d = st + (uint32_t)(row * 144 + seg * 16);
            size_t ao = (size_t)(m0 + row) * K + koff + seg * 8;
            size_t bo = (size_t)(n0 + row) * K + koff + seg * 8;
            cp_async16(d,               Ahi + ao);
            cp_async16(d + GT_TILE,     Alo + ao);
            cp_async16(d + 2 * GT_TILE, Bhi + bo);
            cp_async16(d + 3 * GT_TILE, Blo + bo);
        }
        cp_commit();
    };

    const int a_row = wm * 64 + (lid & 15);
    const int a_colb = (lid >> 4) * 16;
    const int b_row = wn * 32 + ((lid >> 4) << 3) + (lid & 7);
    const int b_colb = ((lid >> 3) & 1) * 16;

    stage(0);
    for (int c = 0; c < nch; c++) {
        if (c + 1 < nch) { stage(c + 1); cp_wait1(); }
        else             { cp_wait0(); }
        __syncthreads();

        const uint32_t st = sb + (uint32_t)(c & 1) * GT_STAGE;
#pragma unroll
        for (int ks = 0; ks < 4; ks++) {
            const int kb = ks * 32;
            uint32_t ah[4][4], al[4][4], bh[2][4], bl[2][4];
#pragma unroll
            for (int mf = 0; mf < 4; mf++) {
                uint32_t addr = st + (uint32_t)((a_row + mf * 16) * 144 + kb + a_colb);
                LDSM_X4(ah[mf], addr);
                LDSM_X4(al[mf], addr + GT_TILE);
            }
#pragma unroll
            for (int nf = 0; nf < 2; nf++) {
                uint32_t addr = st + 2 * GT_TILE +
                                (uint32_t)((b_row + nf * 16) * 144 + kb + b_colb);
                LDSM_X4(bh[nf], addr);
                LDSM_X4(bl[nf], addr + GT_TILE);
            }
#pragma unroll
            for (int mf = 0; mf < 4; mf++)
#pragma unroll
                for (int n8 = 0; n8 < 4; n8++) {
                    const int nf = n8 >> 1, hh = (n8 & 1) * 2;
                    MMA16816(acc[mf][n8], ah[mf], bh[nf][hh], bh[nf][hh + 1]);
                    MMA16816(acc[mf][n8], ah[mf], bl[nf][hh], bl[nf][hh + 1]);
                    MMA16816(acc[mf][n8], al[mf], bh[nf][hh], bh[nf][hh + 1]);
                }
        }
        __syncthreads();
    }

    // epilogue: scatter bias-added scalars into permuted xg [t][cta][b][48]
    auto pstore = [&](int t, int b, int n, float v) {
        int g = n >> 10, j = n & 1023;
        xgp[(((size_t)t * 64 + (j >> 4)) * 64 + b) * 48 + 3 * (j & 15) + g] = v;
    };
#pragma unroll
    for (int mf = 0; mf < 4; mf++) {
        const int gm = m0 + wm * 64 + mf * 16 + (lid >> 2);
        const int b0r = gm >> 9, t0r = gm & 511;
        const int b1r = (gm + 8) >> 9, t1r = (gm + 8) & 511;
#pragma unroll
        for (int n8 = 0; n8 < 4; n8++) {
            const int gc = n0 + wn * 32 + n8 * 8 + (lid & 3) * 2;
            float bb0 = bias[gc], bb1 = bias[gc + 1];
            pstore(t0r, b0r, gc,     acc[mf][n8][0] + bb0);
            pstore(t0r, b0r, gc + 1, acc[mf][n8][1] + bb1);
            pstore(t1r, b1r, gc,     acc[mf][n8][2] + bb0);
            pstore(t1r, b1r, gc + 1, acc[mf][n8][3] + bb1);
        }
    }
}

// ---------------- bulk-staged tensor-core scan, resident Whi --------
// Whi (104.4 KB/CTA) loaded once per layer via a single bulk copy; per step
// stream only Wlo (13 KB/chunk) + h hi/lo (34.8 KB/chunk) + xg (12.3 KB).
#define SN_CTAS    64
#define SN_THREADS 384
#define SB_MB    0                       // 3 mbarriers (24B), pad to 32
#define SB_WHI   32
#define SB_WHI_SZ 104448                 // 8 * 13056
#define SB_WLO   (SB_WHI + SB_WHI_SZ)    // 104480
#define SB_WLOSL 13056
#define SB_A     (SB_WLO + 2 * SB_WLOSL) // 130592
#define SB_ASL   34816                   // hi 17408 + lo 17408
#define SB_XG    (SB_A + 2 * SB_ASL)     // 200224
#define SB_GP    (SB_XG + 12288)         // 212512
#define SB_BH    (SB_GP + 13312)         // 225824
#define SB_TOT   (SB_BH + 192)           // 226016

__device__ __forceinline__ void grid_barrier64(int c) {
    __syncthreads();
    if (threadIdx.x == 0) {
        __threadfence();
        unsigned gen = *(volatile unsigned*)&g_bar_gen;
        int grp = c & 7;
        if (atomicAdd(&g_grp_cnt[grp], 1u) == 7u) {
            if (atomicAdd(&g_root_cnt, 1u) == 7u) {
                atomicExch(&g_root_cnt, 0u);
#pragma unroll
                for (int i = 0; i < 8; i++) atomicExch(&g_grp_cnt[i], 0u);
                __threadfence();
                atomicAdd(&g_bar_gen, 1u);
            }
        }
        while (*(volatile unsigned*)&g_bar_gen == gen) { }
        __threadfence();
    }
    __syncthreads();
}

__global__ __launch_bounds__(SN_THREADS, 1) void scan_bulk_kernel(
    const float* __restrict__ xgp,
    const __nv_bfloat16* __restrict__ wchi, const __nv_bfloat16* __restrict__ wclo,
    const float* __restrict__ bh, float* __restrict__ hout, int write_hout,
    __nv_bfloat16* __restrict__ ahi, __nv_bfloat16* __restrict__ alo,
    float* __restrict__ state_out,
    __nv_bfloat16* __restrict__ hchi, __nv_bfloat16* __restrict__ hclo)
{
    const uint32_t sb = smem_u32(hx_smem);
    float* sXg = (float*)(hx_smem + SB_XG);
    float* sGp = (float*)(hx_smem + SB_GP);
    float* sBh = (float*)(hx_smem + SB_BH);
    const int c = blockIdx.x, tid = threadIdx.x;
    const int wid = tid >> 5, lid = tid & 31;
    const int wm = wid & 3, wn = wid >> 2;          // 4m x 3n warps

    if (tid == 0) {
        MBAR_INIT(sb + SB_MB, 1);
        MBAR_INIT(sb + SB_MB + 8, 1);
        MBAR_INIT(sb + SB_MB + 16, 1);
    }
    if (tid < 48) sBh[tid] = bh[(tid % 3) * H_ + 16 * c + tid / 3];
    __syncthreads();
    // load resident Whi slice (one bulk copy, contiguous per-CTA blocks)
    if (tid == 0) {
        MBAR_EXPECT(sb + SB_MB + 16, (uint32_t)SB_WHI_SZ);
        bulk_g2s(sb + SB_WHI, wchi + (size_t)c * 8 * 48 * 136,
                 (uint32_t)SB_WHI_SZ, sb + SB_MB + 16);
    }
    for (int e = c * SN_THREADS + tid; e < B_ * H_; e += SN_CTAS * SN_THREADS)
        g_h[0][e] = 0.0f;
    for (int e = c * SN_THREADS + tid; e < 8 * B_ * 136; e += SN_CTAS * SN_THREADS) {
        hchi[e] = __float2bfloat16(0.0f);
        hclo[e] = __float2bfloat16(0.0f);
    }
    MBAR_WAIT(sb + SB_MB + 16, 0);
    grid_barrier64(c);

    int ph0 = 0, ph1 = 0;
    const int a_row  = wm * 16 + (lid & 15);
    const int a_colb = (lid >> 4) * 16;
    const int b_row  = wn * 16 + ((lid >> 4) << 3) + (lid & 7);
    const int b_colb = ((lid >> 3) & 1) * 16;

    for (int t = 0; t < T_; t++) {
        const int par = t & 1, nxt = par ^ 1;

        // prefetch old h into registers (fp32 path)
        float ph[3];
#pragma unroll
        for (int it = 0; it < 3; it++) {
            int item = tid + it * SN_THREADS;
            if (item < 1024)
                ph[it] = g_h[par][(item >> 4) * H_ + 16 * c + (item & 15)];
        }

        // issue chunk 0 (+ xg): Wlo + h hi/lo + xg = 60160 bytes
        if (tid == 0) {
            MBAR_EXPECT(sb + SB_MB, 60160u);
            size_t wbase = (size_t)(c * 8) * 48 * 136;
            size_t abase = (size_t)(par * 8) * B_ * 136;
            bulk_g2s(sb + SB_WLO,        wclo + wbase, 13056u, sb + SB_MB);
            bulk_g2s(sb + SB_A,          hchi + abase, 17408u, sb + SB_MB);
            bulk_g2s(sb + SB_A + 17408,  hclo + abase, 17408u, sb + SB_MB);
            bulk_g2s(sb + SB_XG,
                     xgp + ((size_t)t * 64 + c) * 64 * 48, 12288u, sb + SB_MB);
        }

        float acc[2][4];
#pragma unroll
        for (int n8 = 0; n8 < 2; n8++)
#pragma unroll
            for (int q = 0; q < 4; q++) acc[n8][q] = 0.0f;

        for (int ck = 0; ck < 8; ck++) {
            const int s0 = ck & 1;
            if (ck + 1 < 8 && tid == 0) {
                const int s1 = s0 ^ 1;
                const uint32_t mb1 = sb + SB_MB + 8 * s1;
                MBAR_EXPECT(mb1, 47872u);
                size_t wbase = (size_t)(c * 8 + ck + 1) * 48 * 136;
                size_t abase = (size_t)(par * 8 + ck + 1) * B_ * 136;
                bulk_g2s(sb + SB_WLO + s1 * SB_WLOSL,     wclo + wbase, 13056u, mb1);
                bulk_g2s(sb + SB_A + s1 * SB_ASL,         hchi + abase, 17408u, mb1);
                bulk_g2s(sb + SB_A + s1 * SB_ASL + 17408, hclo + abase, 17408u, mb1);
            }
            const uint32_t mb0 = sb + SB_MB + 8 * s0;
            if (s0 == 0) { MBAR_WAIT(mb0, ph0); ph0 ^= 1; }
            else         { MBAR_WAIT(mb0, ph1); ph1 ^= 1; }

            const uint32_t wbhi = sb + SB_WHI + (uint32_t)(ck * SB_WLOSL);
            const uint32_t wblo = sb + SB_WLO + (uint32_t)(s0 * SB_WLOSL);
            const uint32_t ab   = sb + SB_A + (uint32_t)(s0 * SB_ASL);
#pragma unroll
            for (int ks = 0; ks < 8; ks++) {
                const int kb = ks * 32;
                uint32_t ah[4], al[4], bhf[4], blf[4];
                LDSM_X4(ah,  ab + (uint32_t)(a_row * 272 + kb + a_colb));
                LDSM_X4(al,  ab + 17408 + (uint32_t)(a_row * 272 + kb + a_colb));
                LDSM_X4(bhf, wbhi + (uint32_t)(b_row * 272 + kb + b_colb));
                LDSM_X4(blf, wblo + (uint32_t)(b_row * 272 + kb + b_colb));
#pragma unroll
                for (int n8 = 0; n8 < 2; n8++) {
                    MMA16816(acc[n8], ah, bhf[n8 * 2], bhf[n8 * 2 + 1]);
                    MMA16816(acc[n8], ah, blf[n8 * 2], blf[n8 * 2 + 1]);
                    MMA16816(acc[n8], al, bhf[n8 * 2], bhf[n8 * 2 + 1]);
                }
            }
            __syncthreads();          // protect slot reuse
        }

        // epilogue: acc -> smem gate buffer [64][52]
        {
            const int row0 = wm * 16 + (lid >> 2);
#pragma unroll
            for (int n8 = 0; n8 < 2; n8++) {
                const int col = wn * 16 + n8 * 8 + (lid & 3) * 2;
                *(float2*)&sGp[row0 * 52 + col] = make_float2(acc[n8][0], acc[n8][1]);
                *(float2*)&sGp[(row0 + 8) * 52 + col] = make_float2(acc[n8][2], acc[n8][3]);
            }
        }
        __syncthreads();

        // CTA-local GRU update for units [16c, 16c+16)
#pragma unroll
        for (int it = 0; it < 3; it++) {
            int item = tid + it * SN_THREADS;
            if (item < 1024) {
                int b = item >> 4, u = item & 15;
                int j = 16 * c + u;
                float gr = sGp[b * 52 + 3 * u];
                float gz = sGp[b * 52 + 3 * u + 1];
                float gn = sGp[b * 52 + 3 * u + 2];
                float xr = sXg[b * 48 + 3 * u];
                float xz = sXg[b * 48 + 3 * u + 1];
                float xn = sXg[b * 48 + 3 * u + 2];
                float rr = fast_sigmoid(xr + gr + sBh[3 * u]);
                float zz = fast_sigmoid(xz + gz + sBh[3 * u + 1]);
                float nn = fast_tanh(xn + rr * (gn + sBh[3 * u + 2]));
                float hnew = (1.0f - zz) * nn + zz * ph[it];
                size_t row = (size_t)b * T_ + t;
                g_h[nxt][b * H_ + j] = hnew;
                if (write_hout) hout[row * H_ + j] = hnew;
                __nv_bfloat16 hh = __float2bfloat16_rn(hnew);
                __nv_bfloat16 hl = __float2bfloat16_rn(hnew - __bfloat162float(hh));
                int ck2 = j >> 7, kk = j & 127;
                hchi[((size_t)(nxt * 8 + ck2) * B_ + b) * 136 + kk] = hh;
                hclo[((size_t)(nxt * 8 + ck2) * B_ + b) * 136 + kk] = hl;
                ahi[row * H_ + j] = hh;
                alo[row * H_ + j] = hl;
                if (t == T_ - 1) state_out[b * H_ + j] = hnew;
            }
        }
        grid_barrier64(c);
    }
}

// ---------------- launch ----------------
extern "C" void kernel_launch(void* const* d_in, const int* in_sizes, int n_in,
                              void* d_out, int out_size)
{
    const void*  x   = d_in[0];
    const float* emb = (const float*)d_in[1];
    const float* Wx0 = (const float*)d_in[2];
    const float* Wh0 = (const float*)d_in[3];
    const float* bx0 = (const float*)d_in[4];
    const float* bh0 = (const float*)d_in[5];
    const float* Wx  = (const float*)d_in[6];
    const float* Wh  = (const float*)d_in[7];
    const float* bx  = (const float*)d_in[8];
    const float* bh  = (const float*)d_in[9];

    float* out     = (float*)d_out;
    float* enc_out = out;
    float* states  = out + (size_t)M_ * H_;
    float* mask    = states + (size_t)4 * B_ * H_;

    void *p_xg, *p_ahi, *p_alo, *p_whi, *p_wlo, *p_wch, *p_wcl, *p_hch, *p_hcl;
    cudaGetSymbolAddress(&p_xg,  g_xg);
    cudaGetSymbolAddress(&p_ahi, g_ahi);
    cudaGetSymbolAddress(&p_alo, g_alo);
    cudaGetSymbolAddress(&p_whi, g_wthi);
    cudaGetSymbolAddress(&p_wlo, g_wtlo);
    cudaGetSymbolAddress(&p_wch, g_wchi);
    cudaGetSymbolAddress(&p_wcl, g_wclo);
    cudaGetSymbolAddress(&p_hch, g_hc_hi);
    cudaGetSymbolAddress(&p_hcl, g_hc_lo);
    float* xgp = (float*)p_xg;
    __nv_bfloat16* ahi  = (__nv_bfloat16*)p_ahi;
    __nv_bfloat16* alo  = (__nv_bfloat16*)p_alo;
    __nv_bfloat16* whi  = (__nv_bfloat16*)p_whi;
    __nv_bfloat16* wlo  = (__nv_bfloat16*)p_wlo;
    __nv_bfloat16* wchi = (__nv_bfloat16*)p_wch;
    __nv_bfloat16* wclo = (__nv_bfloat16*)p_wcl;
    __nv_bfloat16* hchi = (__nv_bfloat16*)p_hch;
    __nv_bfloat16* hclo = (__nv_bfloat16*)p_hcl;

    cudaFuncSetAttribute(scan_bulk_kernel, cudaFuncAttributeMaxDynamicSharedMemorySize,
                         SB_TOT);
    cudaFuncSetAttribute(gemm_mma_kernel, cudaFuncAttributeMaxDynamicSharedMemorySize,
                         GT_SMEM);

    detect_kernel<<<1, 64>>>((const int*)x);
    embed_kernel<<<M_, 128>>>(x, emb, ahi, alo, mask);

    for (int l = 0; l < 4; l++) {
        const float* WxL = (l == 0) ? Wx0 : Wx + (size_t)(l - 1) * H_ * G3_;
        const float* WhL = (l == 0) ? Wh0 : Wh + (size_t)(l - 1) * H_ * G3_;
        const float* bxL = (l == 0) ? bx0 : bx + (size_t)(l - 1) * G3_;
        const float* bhL = (l == 0) ? bh0 : bh + (size_t)(l - 1) * G3_;
        const int K = (l == 0) ? E_ : H_;

        convertWT_kernel<<<dim3(G3_ / 32, K / 32), 256>>>(WxL, whi, wlo, K);
        gemm_mma_kernel<<<dim3(G3_ / 128, M_ / 128), 256, GT_SMEM>>>(
            ahi, alo, whi, wlo, bxL, xgp, K);
        convertWhc_kernel<<<512, 256>>>(WhL, wchi, wclo);
        scan_bulk_kernel<<<SN_CTAS, SN_THREADS, SB_TOT>>>(
            xgp, wchi, wclo, bhL, enc_out, (l == 3) ? 1 : 0,
            ahi, alo, states + (size_t)l * B_ * H_, hchi, hclo);
    }
}

// round 15
// speedup vs baseline: 1.3958x; 1.1335x over previous
#include <cuda_runtime.h>
#include <cuda_bf16.h>
#include <cstdint>
#include <cmath>

#define B_  64
#define T_  512
#define E_  512
#define H_  1024
#define M_  (B_*T_)     // 32768 rows
#define G3_ (3*H_)      // 3072

extern __shared__ char hx_smem[];

// ---------------- scratch ----------------
__device__ float g_xg [(size_t)M_ * G3_];                // permuted xg: [t][cta128][b][24]
__device__ float g_h[2][B_ * H_];
__device__ __nv_bfloat16 g_hc_hi[2 * 8 * B_ * 136];      // h chunk-major [par][ck][b][136]
__device__ __nv_bfloat16 g_hc_lo[2 * 8 * B_ * 136];
__device__ __nv_bfloat16 g_ahi[(size_t)M_ * H_];
__device__ __nv_bfloat16 g_alo[(size_t)M_ * H_];
__device__ __nv_bfloat16 g_wthi[(size_t)G3_ * H_];       // Wx^T [N][K]
__device__ __nv_bfloat16 g_wtlo[(size_t)G3_ * H_];
__device__ __nv_bfloat16 g_wchi[128 * 8 * 24 * 136];     // Wh per-(cta,ck) blocks
__device__ __nv_bfloat16 g_wclo[128 * 8 * 24 * 136];
__device__ unsigned g_grp_cnt[8];
__device__ unsigned g_root_cnt = 0;
__device__ unsigned g_bar_gen  = 0;
__device__ int g_x_is_i64 = 1;

// ---------------- helpers ----------------
__device__ __forceinline__ float fast_tanh(float x) {
    float y; asm("tanh.approx.f32 %0, %1;" : "=f"(y) : "f"(x)); return y;
}
__device__ __forceinline__ float fast_sigmoid(float x) {
    return 0.5f * fast_tanh(0.5f * x) + 0.5f;
}
__device__ __forceinline__ uint32_t smem_u32(const void* p) {
    return (uint32_t)__cvta_generic_to_shared(p);
}
__device__ __forceinline__ void cp_async16(uint32_t smem_addr, const void* gptr) {
    asm volatile("cp.async.cg.shared.global [%0], [%1], 16;"
                 :: "r"(smem_addr), "l"(gptr));
}
__device__ __forceinline__ void cp_commit() { asm volatile("cp.async.commit_group;"); }
__device__ __forceinline__ void cp_wait0() { asm volatile("cp.async.wait_group 0;"); }
__device__ __forceinline__ void cp_wait1() { asm volatile("cp.async.wait_group 1;"); }

__device__ __forceinline__ void bulk_g2s(uint32_t dst, const void* src,
                                         uint32_t bytes, uint32_t mbar) {
    asm volatile(
        "cp.async.bulk.shared::cluster.global.mbarrier::complete_tx::bytes "
        "[%0], [%1], %2, [%3];"
        :: "r"(dst), "l"(src), "r"(bytes), "r"(mbar) : "memory");
}
#define MBAR_INIT(addr, cnt) \
    asm volatile("mbarrier.init.shared.b64 [%0], %1;" :: "r"(addr), "r"(cnt) : "memory")
#define MBAR_EXPECT(addr, bytes) \
    asm volatile("mbarrier.arrive.expect_tx.shared.b64 _, [%0], %1;" \
                 :: "r"(addr), "r"(bytes) : "memory")
#define MBAR_WAIT(addr, parity) do {                                             \
    asm volatile("{\n\t.reg .pred P1;\n\t"                                       \
        "WAIT_%=:\n\t"                                                           \
        "mbarrier.try_wait.parity.acquire.cta.shared::cta.b64 P1, [%0], %1, 0x989680;\n\t" \
        "@P1 bra.uni DONE_%=;\n\t"                                               \
        "bra.uni WAIT_%=;\n\t"                                                   \
        "DONE_%=:\n\t}"                                                          \
        :: "r"(addr), "r"(parity) : "memory");                                   \
} while (0)

#define LDSM_X4(r, addr) \
    asm volatile("ldmatrix.sync.aligned.m8n8.x4.shared.b16 {%0,%1,%2,%3}, [%4];" \
        : "=r"((r)[0]), "=r"((r)[1]), "=r"((r)[2]), "=r"((r)[3]) : "r"(addr))

#define LDSM_X2(r, addr) \
    asm volatile("ldmatrix.sync.aligned.m8n8.x2.shared.b16 {%0,%1}, [%2];" \
        : "=r"((r)[0]), "=r"((r)[1]) : "r"(addr))

#define MMA16816(d, a, b0, b1) \
    asm volatile("mma.sync.aligned.m16n8k16.row.col.f32.bf16.bf16.f32 " \
        "{%0,%1,%2,%3}, {%4,%5,%6,%7}, {%8,%9}, {%0,%1,%2,%3};" \
        : "+f"((d)[0]), "+f"((d)[1]), "+f"((d)[2]), "+f"((d)[3]) \
        : "r"((a)[0]), "r"((a)[1]), "r"((a)[2]), "r"((a)[3]), "r"(b0), "r"(b1))

// ---------------- int64-vs-int32 detection ----------------
__global__ void detect_kernel(const int* __restrict__ x32) {
    __shared__ int nz;
    if (threadIdx.x == 0) nz = 0;
    __syncthreads();
    if (x32[2 * threadIdx.x + 1] != 0) atomicExch(&nz, 1);
    __syncthreads();
    if (threadIdx.x == 0) g_x_is_i64 = (nz == 0) ? 1 : 0;
}

// ---------------- embedding gather (bf16 hi/lo) + pad mask ----------------
__global__ __launch_bounds__(128) void embed_kernel(
    const void* __restrict__ xraw, const float* __restrict__ emb,
    __nv_bfloat16* __restrict__ ahi, __nv_bfloat16* __restrict__ alo,
    float* __restrict__ mask_out)
{
    const int r = blockIdx.x;
    long long idx;
    if (g_x_is_i64) idx = ((const long long*)xraw)[r];
    else            idx = (long long)((const int*)xraw)[r];
    float4 v = ((const float4*)(emb + (size_t)idx * E_))[threadIdx.x];
    union { __nv_bfloat16 b[4]; uint2 u; } Hh, Ll;
    float f[4] = {v.x, v.y, v.z, v.w};
#pragma unroll
    for (int q = 0; q < 4; q++) {
        __nv_bfloat16 h = __float2bfloat16_rn(f[q]);
        Hh.b[q] = h;
        Ll.b[q] = __float2bfloat16_rn(f[q] - __bfloat162float(h));
    }
    ((uint2*)(ahi + (size_t)r * E_))[threadIdx.x] = Hh.u;
    ((uint2*)(alo + (size_t)r * E_))[threadIdx.x] = Ll.u;
    if (threadIdx.x == 0) mask_out[r] = (idx != 0) ? 1.0f : 0.0f;
}

// ---------------- W [K][3072] fp32 -> W^T [3072][K] bf16 hi/lo (Wx path) ----------------
__global__ __launch_bounds__(256) void convertWT_kernel(
    const float* __restrict__ W, __nv_bfloat16* __restrict__ Thi,
    __nv_bfloat16* __restrict__ Tlo, int K)
{
    __shared__ float t[32][33];
    const int n0 = blockIdx.x * 32, k0 = blockIdx.y * 32;
    const int tx = threadIdx.x & 31, ty = threadIdx.x >> 5;
#pragma unroll
    for (int i = 0; i < 32; i += 8)
        t[ty + i][tx] = W[(size_t)(k0 + ty + i) * G3_ + n0 + tx];
    __syncthreads();
#pragma unroll
    for (int i = 0; i < 32; i += 8) {
        float v = t[tx][ty + i];
        __nv_bfloat16 h = __float2bfloat16_rn(v);
        size_t o = (size_t)(n0 + ty + i) * K + k0 + tx;
        Thi[o] = h;
        Tlo[o] = __float2bfloat16_rn(v - __bfloat162float(h));
    }
}

// ---------------- Wh -> per-(cta128,ck) permuted blocks [24][136] ----------------
__global__ __launch_bounds__(256) void convertWhc_kernel(
    const float* __restrict__ Wh, __nv_bfloat16* __restrict__ wchi,
    __nv_bfloat16* __restrict__ wclo)
{
    __shared__ float tbuf[128][25];
    const int c = blockIdx.x >> 3, ck = blockIdx.x & 7;
    for (int i = threadIdx.x; i < 128 * 24; i += 256) {
        int k = i / 24, col = i % 24;
        int u = col / 3, g = col % 3;
        tbuf[k][col] = Wh[(size_t)(ck * 128 + k) * G3_ + g * H_ + 8 * c + u];
    }
    __syncthreads();
    size_t base = (size_t)blockIdx.x * 24 * 136;
    for (int i = threadIdx.x; i < 24 * 136; i += 256) {
        int q = i / 136, kk = i % 136;
        float v = (kk < 128) ? tbuf[kk][q] : 0.0f;
        __nv_bfloat16 h = __float2bfloat16_rn(v);
        wchi[base + i] = h;
        wclo[base + i] = __float2bfloat16_rn(v - __bfloat162float(h));
    }
}

// ---------------- bf16-split mma.sync GEMM -> permuted xg (+bias) -------
#define GT_TILE   18432                // 128 * 144
#define GT_STAGE  (4 * GT_TILE)
#define GT_SMEM   (2 * GT_STAGE)       // 147456 B

__global__ __launch_bounds__(256, 1) void gemm_mma_kernel(
    const __nv_bfloat16* __restrict__ Ahi, const __nv_bfloat16* __restrict__ Alo,
    const __nv_bfloat16* __restrict__ Bhi, const __nv_bfloat16* __restrict__ Blo,
    const float* __restrict__ bias, float* __restrict__ xgp, int K)
{
    const uint32_t sb = smem_u32(hx_smem);
    const int tid = threadIdx.x;
    const int wid = tid >> 5, lid = tid & 31;
    const int wm = wid & 1, wn = wid >> 1;
    const int n0 = blockIdx.x * 128, m0 = blockIdx.y * 128;
    const int nch = K >> 6;

    float acc[4][4][4];
#pragma unroll
    for (int mf = 0; mf < 4; mf++)
#pragma unroll
        for (int n8 = 0; n8 < 4; n8++)
#pragma unroll
            for (int q = 0; q < 4; q++) acc[mf][n8][q] = 0.0f;

    auto stage = [&](int kc) {
        const uint32_t st = sb + (uint32_t)(kc & 1) * GT_STAGE;
        const int koff = kc * 64;
#pragma unroll
        for (int q = 0; q < 4; q++) {
            int i = tid + 256 * q;
            int row = i >> 3, seg = i & 7;
            uint32_t d = st + (uint32_t)(row * 144 + seg * 16);
            size_t ao = (size_t)(m0 + row) * K + koff + seg * 8;
            size_t bo = (size_t)(n0 + row) * K + koff + seg * 8;
            cp_async16(d,               Ahi + ao);
            cp_async16(d + GT_TILE,     Alo + ao);
            cp_async16(d + 2 * GT_TILE, Bhi + bo);
            cp_async16(d + 3 * GT_TILE, Blo + bo);
        }
        cp_commit();
    };

    const int a_row = wm * 64 + (lid & 15);
    const int a_colb = (lid >> 4) * 16;
    const int b_row = wn * 32 + ((lid >> 4) << 3) + (lid & 7);
    const int b_colb = ((lid >> 3) & 1) * 16;

    stage(0);
    for (int c = 0; c < nch; c++) {
        if (c + 1 < nch) { stage(c + 1); cp_wait1(); }
        else             { cp_wait0(); }
        __syncthreads();

        const uint32_t st = sb + (uint32_t)(c & 1) * GT_STAGE;
#pragma unroll
        for (int ks = 0; ks < 4; ks++) {
            const int kb = ks * 32;
            uint32_t ah[4][4], al[4][4], bh[2][4], bl[2][4];
#pragma unroll
            for (int mf = 0; mf < 4; mf++) {
                uint32_t addr = st + (uint32_t)((a_row + mf * 16) * 144 + kb + a_colb);
                LDSM_X4(ah[mf], addr);
                LDSM_X4(al[mf], addr + GT_TILE);
            }
#pragma unroll
            for (int nf = 0; nf < 2; nf++) {
                uint32_t addr = st + 2 * GT_TILE +
                                (uint32_t)((b_row + nf * 16) * 144 + kb + b_colb);
                LDSM_X4(bh[nf], addr);
                LDSM_X4(bl[nf], addr + GT_TILE);
            }
#pragma unroll
            for (int mf = 0; mf < 4; mf++)
#pragma unroll
                for (int n8 = 0; n8 < 4; n8++) {
                    const int nf = n8 >> 1, hh = (n8 & 1) * 2;
                    MMA16816(acc[mf][n8], ah[mf], bh[nf][hh], bh[nf][hh + 1]);
                    MMA16816(acc[mf][n8], ah[mf], bl[nf][hh], bl[nf][hh + 1]);
                    MMA16816(acc[mf][n8], al[mf], bh[nf][hh], bh[nf][hh + 1]);
                }
        }
        __syncthreads();
    }

    // epilogue: scatter into permuted xg [t][cta128][b][24]
    auto pstore = [&](int t, int b, int n, float v) {
        int g = n >> 10, j = n & 1023;
        xgp[(((size_t)t * 128 + (j >> 3)) * 64 + b) * 24 + 3 * (j & 7) + g] = v;
    };
#pragma unroll
    for (int mf = 0; mf < 4; mf++) {
        const int gm = m0 + wm * 64 + mf * 16 + (lid >> 2);
        const int b0r = gm >> 9, t0r = gm & 511;
        const int b1r = (gm + 8) >> 9, t1r = (gm + 8) & 511;
#pragma unroll
        for (int n8 = 0; n8 < 4; n8++) {
            const int gc = n0 + wn * 32 + n8 * 8 + (lid & 3) * 2;
            float bb0 = bias[gc], bb1 = bias[gc + 1];
            pstore(t0r, b0r, gc,     acc[mf][n8][0] + bb0);
            pstore(t0r, b0r, gc + 1, acc[mf][n8][1] + bb1);
            pstore(t1r, b1r, gc,     acc[mf][n8][2] + bb0);
            pstore(t1r, b1r, gc + 1, acc[mf][n8][3] + bb1);
        }
    }
}

// ---------------- 128-CTA bulk-staged tensor scan, resident Whi --------
#define SN_CTAS    128
#define SN_THREADS 384
#define SB_MB    0                        // 3 mbarriers, pad to 32
#define SB_WHI   32
#define SB_WHI_SZ 52224                   // 8 * 6528
#define SB_WLO   (SB_WHI + SB_WHI_SZ)     // 52256
#define SB_WLOSL 6528                     // 24*272
#define SB_A     (SB_WLO + 2 * SB_WLOSL)  // 65312
#define SB_ASL   34816                    // hi 17408 + lo 17408
#define SB_XG    (SB_A + 2 * SB_ASL)      // 134944
#define SB_GP    (SB_XG + 6144)           // 141088
#define SB_BH    (SB_GP + 7168)           // 148256  ([64][28] floats)
#define SB_TOT   (SB_BH + 96)             // 148352

__device__ __forceinline__ void grid_barrier128(int c) {
    __syncthreads();
    if (threadIdx.x == 0) {
        __threadfence();
        unsigned gen = *(volatile unsigned*)&g_bar_gen;
        int grp = c & 7;                          // 8 groups x 16 CTAs
        if (atomicAdd(&g_grp_cnt[grp], 1u) == 15u) {
            if (atomicAdd(&g_root_cnt, 1u) == 7u) {
                atomicExch(&g_root_cnt, 0u);
#pragma unroll
                for (int i = 0; i < 8; i++) atomicExch(&g_grp_cnt[i], 0u);
                __threadfence();
                atomicAdd(&g_bar_gen, 1u);
            }
        }
        while (*(volatile unsigned*)&g_bar_gen == gen) { }
        __threadfence();
    }
    __syncthreads();
}

__global__ __launch_bounds__(SN_THREADS, 1) void scan_bulk_kernel(
    const float* __restrict__ xgp,
    const __nv_bfloat16* __restrict__ wchi, const __nv_bfloat16* __restrict__ wclo,
    const float* __restrict__ bh, float* __restrict__ hout, int write_hout,
    __nv_bfloat16* __restrict__ ahi, __nv_bfloat16* __restrict__ alo,
    float* __restrict__ state_out,
    __nv_bfloat16* __restrict__ hchi, __nv_bfloat16* __restrict__ hclo)
{
    const uint32_t sb = smem_u32(hx_smem);
    float* sXg = (float*)(hx_smem + SB_XG);
    float* sGp = (float*)(hx_smem + SB_GP);
    float* sBh = (float*)(hx_smem + SB_BH);
    const int c = blockIdx.x, tid = threadIdx.x;
    const int wid = tid >> 5, lid = tid & 31;
    const int wm = wid & 3, wn = wid >> 2;          // 4m x 3n warps, n8 each
    const int l16 = lid & 15;

    if (tid == 0) {
        MBAR_INIT(sb + SB_MB, 1);
        MBAR_INIT(sb + SB_MB + 8, 1);
        MBAR_INIT(sb + SB_MB + 16, 1);
    }
    if (tid < 24) sBh[tid] = bh[(tid % 3) * H_ + 8 * c + tid / 3];
    __syncthreads();
    if (tid == 0) {
        MBAR_EXPECT(sb + SB_MB + 16, (uint32_t)SB_WHI_SZ);
        bulk_g2s(sb + SB_WHI, wchi + (size_t)c * 8 * 24 * 136,
                 (uint32_t)SB_WHI_SZ, sb + SB_MB + 16);
    }
    for (int e = c * SN_THREADS + tid; e < B_ * H_; e += SN_CTAS * SN_THREADS)
        g_h[0][e] = 0.0f;
    for (int e = c * SN_THREADS + tid; e < 8 * B_ * 136; e += SN_CTAS * SN_THREADS) {
        hchi[e] = __float2bfloat16(0.0f);
        hclo[e] = __float2bfloat16(0.0f);
    }
    MBAR_WAIT(sb + SB_MB + 16, 0);
    grid_barrier128(c);

    int ph0 = 0, ph1 = 0;
    const int a_row  = wm * 16 + (lid & 15);
    const int a_colb = (lid >> 4) * 16;
    const int b_row  = wn * 8 + (l16 & 7);
    const int b_colb = ((l16 >> 3) & 1) * 16;

    for (int t = 0; t < T_; t++) {
        const int par = t & 1, nxt = par ^ 1;

        float ph[2];
#pragma unroll
        for (int it = 0; it < 2; it++) {
            int item = tid + it * SN_THREADS;
            if (item < 512)
                ph[it] = g_h[par][(item >> 3) * H_ + 8 * c + (item & 7)];
        }

        // chunk 0 + xg: Wlo 6528 + h 34816 + xg 6144 = 47488
        if (tid == 0) {
            MBAR_EXPECT(sb + SB_MB, 47488u);
            size_t wbase = (size_t)(c * 8) * 24 * 136;
            size_t abase = (size_t)(par * 8) * B_ * 136;
            bulk_g2s(sb + SB_WLO,        wclo + wbase, 6528u,  sb + SB_MB);
            bulk_g2s(sb + SB_A,          hchi + abase, 17408u, sb + SB_MB);
            bulk_g2s(sb + SB_A + 17408,  hclo + abase, 17408u, sb + SB_MB);
            bulk_g2s(sb + SB_XG,
                     xgp + ((size_t)t * 128 + c) * 64 * 24, 6144u, sb + SB_MB);
        }

        float acc[4];
#pragma unroll
        for (int q = 0; q < 4; q++) acc[q] = 0.0f;

        for (int ck = 0; ck < 8; ck++) {
            const int s0 = ck & 1;
            if (ck + 1 < 8 && tid == 0) {
                const int s1 = s0 ^ 1;
                const uint32_t mb1 = sb + SB_MB + 8 * s1;
                MBAR_EXPECT(mb1, 41344u);
                size_t wbase = (size_t)(c * 8 + ck + 1) * 24 * 136;
                size_t abase = (size_t)(par * 8 + ck + 1) * B_ * 136;
                bulk_g2s(sb + SB_WLO + s1 * SB_WLOSL,     wclo + wbase, 6528u,  mb1);
                bulk_g2s(sb + SB_A + s1 * SB_ASL,         hchi + abase, 17408u, mb1);
                bulk_g2s(sb + SB_A + s1 * SB_ASL + 17408, hclo + abase, 17408u, mb1);
            }
            const uint32_t mb0 = sb + SB_MB + 8 * s0;
            if (s0 == 0) { MBAR_WAIT(mb0, ph0); ph0 ^= 1; }
            else         { MBAR_WAIT(mb0, ph1); ph1 ^= 1; }

            const uint32_t wbhi = sb + SB_WHI + (uint32_t)(ck * SB_WLOSL);
            const uint32_t wblo = sb + SB_WLO + (uint32_t)(s0 * SB_WLOSL);
            const uint32_t ab   = sb + SB_A + (uint32_t)(s0 * SB_ASL);
#pragma unroll
            for (int ks = 0; ks < 8; ks++) {
                const int kb = ks * 32;
                uint32_t ah[4], al[4], bhf[2], blf[2];
                LDSM_X4(ah,  ab + (uint32_t)(a_row * 272 + kb + a_colb));
                LDSM_X4(al,  ab + 17408 + (uint32_t)(a_row * 272 + kb + a_colb));
                LDSM_X2(bhf, wbhi + (uint32_t)(b_row * 272 + kb + b_colb));
                LDSM_X2(blf, wblo + (uint32_t)(b_row * 272 + kb + b_colb));
                MMA16816(acc, ah, bhf[0], bhf[1]);
                MMA16816(acc, ah, blf[0], blf[1]);
                MMA16816(acc, al, bhf[0], bhf[1]);
            }
            __syncthreads();
        }

        // epilogue: acc -> smem gate buffer [64][28]
        {
            const int row0 = wm * 16 + (lid >> 2);
            const int col = wn * 8 + (lid & 3) * 2;
            *(float2*)&sGp[row0 * 28 + col] = make_float2(acc[0], acc[1]);
            *(float2*)&sGp[(row0 + 8) * 28 + col] = make_float2(acc[2], acc[3]);
        }
        __syncthreads();

        // CTA-local GRU update for units [8c, 8c+8)
#pragma unroll
        for (int it = 0; it < 2; it++) {
            int item = tid + it * SN_THREADS;
            if (item < 512) {
                int b = item >> 3, u = item & 7;
                int j = 8 * c + u;
                float gr = sGp[b * 28 + 3 * u];
                float gz = sGp[b * 28 + 3 * u + 1];
                float gn = sGp[b * 28 + 3 * u + 2];
                float xr = sXg[b * 24 + 3 * u];
                float xz = sXg[b * 24 + 3 * u + 1];
                float xn = sXg[b * 24 + 3 * u + 2];
                float rr = fast_sigmoid(xr + gr + sBh[3 * u]);
                float zz = fast_sigmoid(xz + gz + sBh[3 * u + 1]);
                float nn = fast_tanh(xn + rr * (gn + sBh[3 * u + 2]));
                float hnew = (1.0f - zz) * nn + zz * ph[it];
                size_t row = (size_t)b * T_ + t;
                g_h[nxt][b * H_ + j] = hnew;
                if (write_hout) hout[row * H_ + j] = hnew;
                __nv_bfloat16 hh = __float2bfloat16_rn(hnew);
                __nv_bfloat16 hl = __float2bfloat16_rn(hnew - __bfloat162float(hh));
                int ck2 = j >> 7, kk = j & 127;
                hchi[((size_t)(nxt * 8 + ck2) * B_ + b) * 136 + kk] = hh;
                hclo[((size_t)(nxt * 8 + ck2) * B_ + b) * 136 + kk] = hl;
                ahi[row * H_ + j] = hh;
                alo[row * H_ + j] = hl;
                if (t == T_ - 1) state_out[b * H_ + j] = hnew;
            }
        }
        grid_barrier128(c);
    }
}

// ---------------- launch ----------------
extern "C" void kernel_launch(void* const* d_in, const int* in_sizes, int n_in,
                              void* d_out, int out_size)
{
    const void*  x   = d_in[0];
    const float* emb = (const float*)d_in[1];
    const float* Wx0 = (const float*)d_in[2];
    const float* Wh0 = (const float*)d_in[3];
    const float* bx0 = (const float*)d_in[4];
    const float* bh0 = (const float*)d_in[5];
    const float* Wx  = (const float*)d_in[6];
    const float* Wh  = (const float*)d_in[7];
    const float* bx  = (const float*)d_in[8];
    const float* bh  = (const float*)d_in[9];

    float* out     = (float*)d_out;
    float* enc_out = out;
    float* states  = out + (size_t)M_ * H_;
    float* mask    = states + (size_t)4 * B_ * H_;

    void *p_xg, *p_ahi, *p_alo, *p_whi, *p_wlo, *p_wch, *p_wcl, *p_hch, *p_hcl;
    cudaGetSymbolAddress(&p_xg,  g_xg);
    cudaGetSymbolAddress(&p_ahi, g_ahi);
    cudaGetSymbolAddress(&p_alo, g_alo);
    cudaGetSymbolAddress(&p_whi, g_wthi);
    cudaGetSymbolAddress(&p_wlo, g_wtlo);
    cudaGetSymbolAddress(&p_wch, g_wchi);
    cudaGetSymbolAddress(&p_wcl, g_wclo);
    cudaGetSymbolAddress(&p_hch, g_hc_hi);
    cudaGetSymbolAddress(&p_hcl, g_hc_lo);
    float* xgp = (float*)p_xg;
    __nv_bfloat16* ahi  = (__nv_bfloat16*)p_ahi;
    __nv_bfloat16* alo  = (__nv_bfloat16*)p_alo;
    __nv_bfloat16* whi  = (__nv_bfloat16*)p_whi;
    __nv_bfloat16* wlo  = (__nv_bfloat16*)p_wlo;
    __nv_bfloat16* wchi = (__nv_bfloat16*)p_wch;
    __nv_bfloat16* wclo = (__nv_bfloat16*)p_wcl;
    __nv_bfloat16* hchi = (__nv_bfloat16*)p_hch;
    __nv_bfloat16* hclo = (__nv_bfloat16*)p_hcl;

    cudaFuncSetAttribute(scan_bulk_kernel, cudaFuncAttributeMaxDynamicSharedMemorySize,
                         SB_TOT);
    cudaFuncSetAttribute(gemm_mma_kernel, cudaFuncAttributeMaxDynamicSharedMemorySize,
                         GT_SMEM);

    detect_kernel<<<1, 64>>>((const int*)x);
    embed_kernel<<<M_, 128>>>(x, emb, ahi, alo, mask);

    for (int l = 0; l < 4; l++) {
        const float* WxL = (l == 0) ? Wx0 : Wx + (size_t)(l - 1) * H_ * G3_;
        const float* WhL = (l == 0) ? Wh0 : Wh + (size_t)(l - 1) * H_ * G3_;
        const float* bxL = (l == 0) ? bx0 : bx + (size_t)(l - 1) * G3_;
        const float* bhL = (l == 0) ? bh0 : bh + (size_t)(l - 1) * G3_;
        const int K = (l == 0) ? E_ : H_;

        convertWT_kernel<<<dim3(G3_ / 32, K / 32), 256>>>(WxL, whi, wlo, K);
        gemm_mma_kernel<<<dim3(G3_ / 128, M_ / 128), 256, GT_SMEM>>>(
            ahi, alo, whi, wlo, bxL, xgp, K);
        convertWhc_kernel<<<1024, 256>>>(WhL, wchi, wclo);
        scan_bulk_kernel<<<SN_CTAS, SN_THREADS, SB_TOT>>>(
            xgp, wchi, wclo, bhL, enc_out, (l == 3) ? 1 : 0,
            ahi, alo, states + (size_t)l * B_ * H_, hchi, hclo);
    }
}